// round 1
// baseline (speedup 1.0000x reference)
#include <cuda_runtime.h>
#include <cstdint>
#include <cstddef>

// ---------------------------------------------------------------------------
// CrossAttentionDecoder: B=1024 (8*128), n_tok=16, num_latents=128, d=512,
// heads=8, dh=64.  Mask: batch b attends only to latents j <= (b % 128).
//
// Pipeline (5 launches, all tf32 tensor-core GEMMs except attention):
//   1. Q  = x  @ Wq^T              (16384 x 512)
//   2. K  = l  @ Wk^T  (masked row-block skip)   (131072 x 512)
//   3. V  = l  @ Wv^T  (masked row-block skip)
//   4. attention per (b, h): softmax(QK^T/8 + mask) V  -> g_A
//   5. out = g_A @ Wo^T + bo  -> d_out
// ---------------------------------------------------------------------------

#define DIMK 512

// Scratch (allocation-free: __device__ globals)
__device__ float g_Q[1024 * 16 * 512];    //  32 MB
__device__ float g_K[1024 * 128 * 512];   // 256 MB
__device__ float g_V[1024 * 128 * 512];   // 256 MB
__device__ float g_A[1024 * 16 * 512];    //  32 MB

__device__ __forceinline__ float to_tf32(float x) {
    uint32_t u;
    asm("cvt.rna.tf32.f32 %0, %1;" : "=r"(u) : "f"(x));
    return __uint_as_float(u);
}

__device__ __forceinline__ void mma_tf32(float* d, const uint32_t* a, const uint32_t* b) {
    asm volatile(
        "mma.sync.aligned.m16n8k8.row.col.f32.tf32.tf32.f32 "
        "{%0,%1,%2,%3}, {%4,%5,%6,%7}, {%8,%9}, {%0,%1,%2,%3};\n"
        : "+f"(d[0]), "+f"(d[1]), "+f"(d[2]), "+f"(d[3])
        : "r"(a[0]), "r"(a[1]), "r"(a[2]), "r"(a[3]),
          "r"(b[0]), "r"(b[1]));
}

// ---------------------------------------------------------------------------
// C[M x 512] = A[M x 512] @ W[512 x 512]^T  (+ optional bias)
// BM=128, BN=64, BK=32.  256 threads = 8 warps laid out 4(m) x 2(n);
// warp tile 32x32 = 2 m16 x 4 n8 mma tiles.
// masked != 0: block m-tile index == batch b; rows beyond (b%128)+1 skipped
// at whole-warp (32-row) granularity.
// ---------------------------------------------------------------------------
__global__ __launch_bounds__(256)
void gemm_awt(const float* __restrict__ A, const float* __restrict__ W,
              const float* __restrict__ bias, float* __restrict__ C, int masked)
{
    __shared__ float As[128][36];
    __shared__ float Ws[64][36];

    const int row0 = blockIdx.x * 128;
    const int col0 = blockIdx.y * 64;
    int valid = 128;
    if (masked) valid = (int)(blockIdx.x & 127) + 1;

    const int tid  = threadIdx.x;
    const int warp = tid >> 5, lane = tid & 31;
    const int wm = warp >> 1, wn = warp & 1;
    const int g  = lane >> 2, tg = lane & 3;
    const bool active = (wm * 32) < valid;

    float acc[2][4][4];
    #pragma unroll
    for (int i = 0; i < 2; i++)
        #pragma unroll
        for (int j = 0; j < 4; j++)
            #pragma unroll
            for (int c = 0; c < 4; c++) acc[i][j][c] = 0.f;

    for (int k0 = 0; k0 < DIMK; k0 += 32) {
        // stage A tile (128x32) — tf32-round on the way in
        #pragma unroll
        for (int i = 0; i < 4; i++) {
            int idx = tid + i * 256;
            int r_ = idx >> 3, c_ = (idx & 7) << 2;
            float4 v = *(const float4*)(A + (size_t)(row0 + r_) * DIMK + k0 + c_);
            As[r_][c_ + 0] = to_tf32(v.x);
            As[r_][c_ + 1] = to_tf32(v.y);
            As[r_][c_ + 2] = to_tf32(v.z);
            As[r_][c_ + 3] = to_tf32(v.w);
        }
        // stage W tile (64x32)
        #pragma unroll
        for (int i = 0; i < 2; i++) {
            int idx = tid + i * 256;
            int r_ = idx >> 3, c_ = (idx & 7) << 2;
            float4 v = *(const float4*)(W + (size_t)(col0 + r_) * DIMK + k0 + c_);
            Ws[r_][c_ + 0] = to_tf32(v.x);
            Ws[r_][c_ + 1] = to_tf32(v.y);
            Ws[r_][c_ + 2] = to_tf32(v.z);
            Ws[r_][c_ + 3] = to_tf32(v.w);
        }
        __syncthreads();

        if (active) {
            #pragma unroll
            for (int kk = 0; kk < 4; kk++) {
                const int kb = kk * 8;
                uint32_t a[2][4], b[4][2];
                #pragma unroll
                for (int mt = 0; mt < 2; mt++) {
                    int rb = wm * 32 + mt * 16;
                    a[mt][0] = __float_as_uint(As[rb + g    ][kb + tg    ]);
                    a[mt][1] = __float_as_uint(As[rb + g + 8][kb + tg    ]);
                    a[mt][2] = __float_as_uint(As[rb + g    ][kb + tg + 4]);
                    a[mt][3] = __float_as_uint(As[rb + g + 8][kb + tg + 4]);
                }
                #pragma unroll
                for (int nt = 0; nt < 4; nt++) {
                    int nb = wn * 32 + nt * 8;
                    b[nt][0] = __float_as_uint(Ws[nb + g][kb + tg    ]);
                    b[nt][1] = __float_as_uint(Ws[nb + g][kb + tg + 4]);
                }
                #pragma unroll
                for (int mt = 0; mt < 2; mt++)
                    #pragma unroll
                    for (int nt = 0; nt < 4; nt++)
                        mma_tf32(acc[mt][nt], a[mt], b[nt]);
            }
        }
        __syncthreads();
    }

    if (!active) return;
    #pragma unroll
    for (int mt = 0; mt < 2; mt++) {
        int rr = row0 + wm * 32 + mt * 16 + g;
        #pragma unroll
        for (int nt = 0; nt < 4; nt++) {
            int cc = col0 + wn * 32 + nt * 8 + 2 * tg;
            float b0 = bias ? bias[cc]     : 0.f;
            float b1 = bias ? bias[cc + 1] : 0.f;
            C[(size_t)rr * DIMK + cc]           = acc[mt][nt][0] + b0;
            C[(size_t)rr * DIMK + cc + 1]       = acc[mt][nt][1] + b1;
            C[(size_t)(rr + 8) * DIMK + cc]     = acc[mt][nt][2] + b0;
            C[(size_t)(rr + 8) * DIMK + cc + 1] = acc[mt][nt][3] + b1;
        }
    }
}

// ---------------------------------------------------------------------------
// Attention: one CTA per (b, h).  Q 16x64, K/V (r+1)x64 in smem.
// Scores row-padded to stride 129 (kills 16-way softmax bank conflicts).
// ---------------------------------------------------------------------------
#define PS 129

__global__ __launch_bounds__(256)
void attn_kernel(const float* __restrict__ Q, const float* __restrict__ K,
                 const float* __restrict__ V, float* __restrict__ O)
{
    const int b = blockIdx.x, h = blockIdx.y;
    const int r = b & 127, nj = r + 1;

    extern __shared__ float sm[];
    float* Qs = sm;                    // 16*64
    float* Ks = Qs + 16 * 64;          // 128*64
    float* Vs = Ks + 128 * 64;         // 128*64
    float* Ps = Vs + 128 * 64;         // 16*PS

    const int tid = threadIdx.x;

    const float* Qg = Q + (size_t)b * 16 * 512 + h * 64;
    for (int i = tid; i < 16 * 16; i += 256) {
        int row = i >> 4, c4 = (i & 15) << 2;
        *(float4*)(Qs + row * 64 + c4) = *(const float4*)(Qg + row * 512 + c4);
    }
    const float* Kg = K + (size_t)b * 128 * 512 + h * 64;
    const float* Vg = V + (size_t)b * 128 * 512 + h * 64;
    for (int i = tid; i < nj * 16; i += 256) {
        int row = i >> 4, c4 = (i & 15) << 2;
        *(float4*)(Ks + row * 64 + c4) = *(const float4*)(Kg + row * 512 + c4);
        *(float4*)(Vs + row * 64 + c4) = *(const float4*)(Vg + row * 512 + c4);
    }
    __syncthreads();

    // scores: thread t -> token i = t>>4, latents j = (t&15), step 16
    {
        const int i = tid >> 4;
        const float* q = Qs + i * 64;
        for (int j = tid & 15; j < nj; j += 16) {
            const float* k = Ks + j * 64;
            float s = 0.f;
            #pragma unroll
            for (int c = 0; c < 64; c += 4) {
                float4 qv = *(const float4*)(q + c);
                float4 kv = *(const float4*)(k + c);
                s += qv.x * kv.x + qv.y * kv.y + qv.z * kv.z + qv.w * kv.w;
            }
            Ps[i * PS + j] = s * 0.125f;   // dh^-0.5 = 1/8
        }
    }
    __syncthreads();

    // softmax over j in [0, nj): one thread per token row
    if (tid < 16) {
        float* p = Ps + tid * PS;
        float m = -1e30f;
        for (int j = 0; j < nj; j++) m = fmaxf(m, p[j]);
        float sum = 0.f;
        for (int j = 0; j < nj; j++) { float e = __expf(p[j] - m); p[j] = e; sum += e; }
        float inv = 1.0f / sum;
        for (int j = 0; j < nj; j++) p[j] *= inv;
    }
    __syncthreads();

    // out(i,c) = sum_j P[i][j] * V[j][c];  thread t -> c = t&63, i block = t>>6
    {
        const int c = tid & 63, qd = tid >> 6;
        float acc[4] = {0.f, 0.f, 0.f, 0.f};
        for (int j = 0; j < nj; j++) {
            float v = Vs[j * 64 + c];
            #pragma unroll
            for (int k = 0; k < 4; k++)
                acc[k] += Ps[(qd * 4 + k) * PS + j] * v;
        }
        float* Og = O + (size_t)b * 16 * 512 + h * 64;
        #pragma unroll
        for (int k = 0; k < 4; k++)
            Og[(size_t)(qd * 4 + k) * 512 + c] = acc[k];
    }
}

// ---------------------------------------------------------------------------
extern "C" void kernel_launch(void* const* d_in, const int* in_sizes, int n_in,
                              void* d_out, int out_size)
{
    const float* x  = (const float*)d_in[0];
    const float* l  = (const float*)d_in[1];
    const float* Wq = (const float*)d_in[2];
    const float* Wk = (const float*)d_in[3];
    const float* Wv = (const float*)d_in[4];
    const float* Wo = (const float*)d_in[5];
    const float* bo = (const float*)d_in[6];
    float* out = (float*)d_out;

    float *Qp, *Kp, *Vp, *Ap;
    cudaGetSymbolAddress((void**)&Qp, g_Q);
    cudaGetSymbolAddress((void**)&Kp, g_K);
    cudaGetSymbolAddress((void**)&Vp, g_V);
    cudaGetSymbolAddress((void**)&Ap, g_A);

    const int attn_smem = (16 * 64 + 128 * 64 + 128 * 64 + 16 * PS) * (int)sizeof(float);
    cudaFuncSetAttribute(attn_kernel, cudaFuncAttributeMaxDynamicSharedMemorySize, attn_smem);

    dim3 blk(256);
    // 1. Q projection (dense)
    gemm_awt<<<dim3(128, 8), blk>>>(x, Wq, nullptr, Qp, 0);
    // 2/3. K and V projections (mask-aware row-block skip)
    gemm_awt<<<dim3(1024, 8), blk>>>(l, Wk, nullptr, Kp, 1);
    gemm_awt<<<dim3(1024, 8), blk>>>(l, Wv, nullptr, Vp, 1);
    // 4. masked attention
    attn_kernel<<<dim3(1024, 8), blk, attn_smem>>>(Qp, Kp, Vp, Ap);
    // 5. output projection + bias -> d_out
    gemm_awt<<<dim3(128, 8), blk>>>(Ap, Wo, bo, out, 0);
}

// round 2
// speedup vs baseline: 2.0526x; 2.0526x over previous
#include <cuda_runtime.h>
#include <cstdint>
#include <cstddef>

// ---------------------------------------------------------------------------
// CrossAttentionDecoder: B=1024 (8*128), n_tok=16, num_latents=128, d=512,
// heads=8, dh=64.  Mask: batch b attends only to latents j <= (b % 128).
//
// Pipeline:
//   0. prep: Wq/Wk/Wv/Wo -> tf32 (device global)
//   1. Q = x @ Wq^T                      gemm<1>
//   2. K,V = l @ Wk^T, l @ Wv^T fused    gemm<2>, masked row-block skip
//   3. attention per (b,h), tensor-core  attn_kernel
//   4. out = A @ Wo^T + bo               gemm<1>
// ---------------------------------------------------------------------------

#define DIMK 512

__device__ float g_Q[1024 * 16 * 512];
__device__ float g_K[1024 * 128 * 512];
__device__ float g_V[1024 * 128 * 512];
__device__ float g_A[1024 * 16 * 512];
__device__ float g_Wt[4][512 * 512];   // tf32-preconverted Wq, Wk, Wv, Wo

__device__ __forceinline__ float to_tf32(float x) {
    uint32_t u; asm("cvt.rna.tf32.f32 %0, %1;" : "=r"(u) : "f"(x));
    return __uint_as_float(u);
}
__device__ __forceinline__ uint32_t to_tf32u(float x) {
    uint32_t u; asm("cvt.rna.tf32.f32 %0, %1;" : "=r"(u) : "f"(x));
    return u;
}

__device__ __forceinline__ void mma_tf32(float* d, const uint32_t* a, const uint32_t* b) {
    asm volatile(
        "mma.sync.aligned.m16n8k8.row.col.f32.tf32.tf32.f32 "
        "{%0,%1,%2,%3}, {%4,%5,%6,%7}, {%8,%9}, {%0,%1,%2,%3};\n"
        : "+f"(d[0]), "+f"(d[1]), "+f"(d[2]), "+f"(d[3])
        : "r"(a[0]), "r"(a[1]), "r"(a[2]), "r"(a[3]),
          "r"(b[0]), "r"(b[1]));
}

__device__ __forceinline__ void cp_async16(void* sdst, const void* gsrc) {
    uint32_t d = (uint32_t)__cvta_generic_to_shared(sdst);
    asm volatile("cp.async.ca.shared.global [%0], [%1], 16;\n" :: "r"(d), "l"(gsrc));
}
__device__ __forceinline__ void cp_commit() { asm volatile("cp.async.commit_group;\n"); }
__device__ __forceinline__ void cp_wait0()  { asm volatile("cp.async.wait_group 0;\n"); }

// ---------------------------------------------------------------------------
__global__ __launch_bounds__(256)
void prep_w(const float* __restrict__ Wq, const float* __restrict__ Wk,
            const float* __restrict__ Wv, const float* __restrict__ Wo)
{
    int i = blockIdx.x * 256 + threadIdx.x;   // grid 1024 -> 262144
    g_Wt[0][i] = to_tf32(Wq[i]);
    g_Wt[1][i] = to_tf32(Wk[i]);
    g_Wt[2][i] = to_tf32(Wv[i]);
    g_Wt[3][i] = to_tf32(Wo[i]);
}

// ---------------------------------------------------------------------------
// C[M x 512] = A[M x 512] @ W^T (+ bias), optionally two W/two C fused.
// BM=128, BN=64, BK=32; 8 warps 4(m)x2(n), warp tile 32x32 per output.
// Double-buffered smem via cp.async; W is pre-converted tf32, A cvt at frag load.
// masked: m-tile index b -> only rows < (b&127)+1 needed; skip at warp (32-row) grain.
// Dyn smem: As 2*128*36 floats, then Ws 2*NOUT*64*36 floats.
// ---------------------------------------------------------------------------
template <int NOUT>
__global__ __launch_bounds__(256)
void gemm_kernel(const float* __restrict__ A,
                 const float* __restrict__ W0, const float* __restrict__ W1,
                 float* __restrict__ C0, float* __restrict__ C1,
                 const float* __restrict__ bias, int masked)
{
    extern __shared__ float sm[];
    float* As = sm;                     // [2][128][36]
    float* Ws = sm + 2 * 128 * 36;      // [2][NOUT][64][36]

    const int row0 = blockIdx.x * 128;
    const int col0 = blockIdx.y * 64;
    const int valid = masked ? (int)(blockIdx.x & 127) + 1 : 128;

    const int tid = threadIdx.x;
    const int warp = tid >> 5, lane = tid & 31;
    const int wm = warp >> 1, wn = warp & 1;
    const int g = lane >> 2, tg = lane & 3;
    const bool active = (wm * 32) < valid;

    float acc[NOUT][2][4][4];
    #pragma unroll
    for (int o = 0; o < NOUT; o++)
        #pragma unroll
        for (int i = 0; i < 2; i++)
            #pragma unroll
            for (int j = 0; j < 4; j++)
                #pragma unroll
                for (int c = 0; c < 4; c++) acc[o][i][j][c] = 0.f;

    // ---- prologue: stage k=0 into buffer 0 ----
    {
        #pragma unroll
        for (int i = 0; i < 4; i++) {
            int idx = tid + i * 256;
            int r = idx >> 3, c = (idx & 7) << 2;
            cp_async16(&As[r * 36 + c], A + (size_t)(row0 + r) * DIMK + c);
        }
        #pragma unroll
        for (int i = 0; i < 2; i++) {
            int idx = tid + i * 256;
            int r = idx >> 3, c = (idx & 7) << 2;
            cp_async16(&Ws[r * 36 + c], W0 + (size_t)(col0 + r) * DIMK + c);
            if (NOUT == 2)
                cp_async16(&Ws[64 * 36 + r * 36 + c], W1 + (size_t)(col0 + r) * DIMK + c);
        }
        cp_commit(); cp_wait0();
        __syncthreads();
    }

    for (int it = 0; it < 16; ++it) {
        const int cur = it & 1;
        float* Ac = As + cur * (128 * 36);
        float* Wc = Ws + cur * (NOUT * 64 * 36);

        if (it < 15) {
            const int nb = cur ^ 1;
            const int nk = (it + 1) * 32;
            float* An = As + nb * (128 * 36);
            float* Wn = Ws + nb * (NOUT * 64 * 36);
            #pragma unroll
            for (int i = 0; i < 4; i++) {
                int idx = tid + i * 256;
                int r = idx >> 3, c = (idx & 7) << 2;
                cp_async16(&An[r * 36 + c], A + (size_t)(row0 + r) * DIMK + nk + c);
            }
            #pragma unroll
            for (int i = 0; i < 2; i++) {
                int idx = tid + i * 256;
                int r = idx >> 3, c = (idx & 7) << 2;
                cp_async16(&Wn[r * 36 + c], W0 + (size_t)(col0 + r) * DIMK + nk + c);
                if (NOUT == 2)
                    cp_async16(&Wn[64 * 36 + r * 36 + c], W1 + (size_t)(col0 + r) * DIMK + nk + c);
            }
            cp_commit();
        }

        if (active) {
            #pragma unroll
            for (int kk = 0; kk < 4; kk++) {
                const int kb = kk * 8;
                uint32_t a[2][4];
                #pragma unroll
                for (int mt = 0; mt < 2; mt++) {
                    int rb = wm * 32 + mt * 16;
                    a[mt][0] = to_tf32u(Ac[(rb + g) * 36 + kb + tg]);
                    a[mt][1] = to_tf32u(Ac[(rb + g + 8) * 36 + kb + tg]);
                    a[mt][2] = to_tf32u(Ac[(rb + g) * 36 + kb + tg + 4]);
                    a[mt][3] = to_tf32u(Ac[(rb + g + 8) * 36 + kb + tg + 4]);
                }
                #pragma unroll
                for (int o = 0; o < NOUT; o++) {
                    const float* Wb = Wc + o * (64 * 36);
                    #pragma unroll
                    for (int nt = 0; nt < 4; nt++) {
                        int nb_ = wn * 32 + nt * 8;
                        uint32_t b[2];
                        b[0] = __float_as_uint(Wb[(nb_ + g) * 36 + kb + tg]);
                        b[1] = __float_as_uint(Wb[(nb_ + g) * 36 + kb + tg + 4]);
                        #pragma unroll
                        for (int mt = 0; mt < 2; mt++)
                            mma_tf32(acc[o][mt][nt], a[mt], b);
                    }
                }
            }
        }

        if (it < 15) cp_wait0();
        __syncthreads();
    }

    if (!active) return;
    #pragma unroll
    for (int o = 0; o < NOUT; o++) {
        float* C = (o == 0) ? C0 : C1;
        #pragma unroll
        for (int mt = 0; mt < 2; mt++) {
            int rr = row0 + wm * 32 + mt * 16 + g;
            #pragma unroll
            for (int nt = 0; nt < 4; nt++) {
                int cc = col0 + wn * 32 + nt * 8 + 2 * tg;
                float b0 = bias ? bias[cc] : 0.f;
                float b1 = bias ? bias[cc + 1] : 0.f;
                C[(size_t)rr * DIMK + cc]           = acc[o][mt][nt][0] + b0;
                C[(size_t)rr * DIMK + cc + 1]       = acc[o][mt][nt][1] + b1;
                C[(size_t)(rr + 8) * DIMK + cc]     = acc[o][mt][nt][2] + b0;
                C[(size_t)(rr + 8) * DIMK + cc + 1] = acc[o][mt][nt][3] + b1;
            }
        }
    }
}

// ---------------------------------------------------------------------------
// Attention, tensor-core.  One CTA per (b,h), 256 threads = 8 warps.
// Smem strides chosen conflict-free:  Qs/Ks 76, Vs 72, Ps 132.
// ---------------------------------------------------------------------------
__global__ __launch_bounds__(256)
void attn_kernel(const float* __restrict__ Q, const float* __restrict__ K,
                 const float* __restrict__ V, float* __restrict__ O)
{
    const int b = blockIdx.x, h = blockIdx.y;
    const int r = b & 127, nj = r + 1;
    const int njp8 = (nj + 7) & ~7;

    extern __shared__ float sm[];
    float* Qs = sm;                 // 16 x 76
    float* Ks = Qs + 16 * 76;       // 128 x 76
    float* Vs = Ks + 128 * 76;      // 128 x 72
    float* Ps = Vs + 128 * 72;      // 16 x 132

    const int tid = threadIdx.x;
    const int warp = tid >> 5, lane = tid & 31;
    const int g = lane >> 2, tg = lane & 3;

    // stage Q (tf32)
    {
        int row = tid >> 4, c4 = (tid & 15) << 2;
        float4 v = *(const float4*)(Q + (size_t)b * 16 * 512 + (size_t)row * 512 + h * 64 + c4);
        float* d = Qs + row * 76 + c4;
        d[0] = to_tf32(v.x); d[1] = to_tf32(v.y); d[2] = to_tf32(v.z); d[3] = to_tf32(v.w);
    }
    // stage K, V (tf32)
    const float* Kg = K + (size_t)b * 128 * 512 + h * 64;
    const float* Vg = V + (size_t)b * 128 * 512 + h * 64;
    for (int i = tid; i < nj * 16; i += 256) {
        int row = i >> 4, c4 = (i & 15) << 2;
        float4 kv = *(const float4*)(Kg + (size_t)row * 512 + c4);
        float4 vv = *(const float4*)(Vg + (size_t)row * 512 + c4);
        float* kd = Ks + row * 76 + c4;
        kd[0] = to_tf32(kv.x); kd[1] = to_tf32(kv.y); kd[2] = to_tf32(kv.z); kd[3] = to_tf32(kv.w);
        float* vd = Vs + row * 72 + c4;
        vd[0] = to_tf32(vv.x); vd[1] = to_tf32(vv.y); vd[2] = to_tf32(vv.z); vd[3] = to_tf32(vv.w);
    }
    __syncthreads();

    // scores S = (Q K^T) / 8  via mma; warp w covers cols [8w,8w+8) and [8w+64,...)
    #pragma unroll
    for (int t = 0; t < 2; t++) {
        int n0 = warp * 8 + t * 64;
        if (n0 < njp8) {
            float dacc[4] = {0.f, 0.f, 0.f, 0.f};
            #pragma unroll
            for (int kb = 0; kb < 64; kb += 8) {
                uint32_t a[4], bf[2];
                a[0] = __float_as_uint(Qs[g * 76 + kb + tg]);
                a[1] = __float_as_uint(Qs[(g + 8) * 76 + kb + tg]);
                a[2] = __float_as_uint(Qs[g * 76 + kb + tg + 4]);
                a[3] = __float_as_uint(Qs[(g + 8) * 76 + kb + tg + 4]);
                bf[0] = __float_as_uint(Ks[(n0 + g) * 76 + kb + tg]);
                bf[1] = __float_as_uint(Ks[(n0 + g) * 76 + kb + tg + 4]);
                mma_tf32(dacc, a, bf);
            }
            Ps[g * 132 + n0 + 2 * tg]         = dacc[0] * 0.125f;
            Ps[g * 132 + n0 + 2 * tg + 1]     = dacc[1] * 0.125f;
            Ps[(g + 8) * 132 + n0 + 2 * tg]     = dacc[2] * 0.125f;
            Ps[(g + 8) * 132 + n0 + 2 * tg + 1] = dacc[3] * 0.125f;
        }
    }
    __syncthreads();

    // softmax over j<nj, rows 2*warp, 2*warp+1; probs -> tf32, pad zeros to njp8
    #pragma unroll
    for (int rr = 0; rr < 2; rr++) {
        int row = warp * 2 + rr;
        float* p = Ps + row * 132;
        float m = -1e30f;
        for (int j = lane; j < nj; j += 32) m = fmaxf(m, p[j]);
        #pragma unroll
        for (int o = 16; o; o >>= 1) m = fmaxf(m, __shfl_xor_sync(0xffffffffu, m, o));
        float e[4]; int cnt = 0; float s = 0.f;
        for (int j = lane; j < nj; j += 32) { float ev = __expf(p[j] - m); e[cnt++] = ev; s += ev; }
        #pragma unroll
        for (int o = 16; o; o >>= 1) s += __shfl_xor_sync(0xffffffffu, s, o);
        float inv = 1.f / s;
        cnt = 0;
        for (int j = lane; j < njp8; j += 32) {
            float val = (j < nj) ? e[cnt++] * inv : 0.f;
            p[j] = to_tf32(val);
        }
    }
    __syncthreads();

    // O = P V via mma; warp w -> output cols [8w, 8w+8)
    {
        int n0 = warp * 8;
        float dacc[4] = {0.f, 0.f, 0.f, 0.f};
        for (int kb = 0; kb < njp8; kb += 8) {
            uint32_t a[4], bf[2];
            a[0] = __float_as_uint(Ps[g * 132 + kb + tg]);
            a[1] = __float_as_uint(Ps[(g + 8) * 132 + kb + tg]);
            a[2] = __float_as_uint(Ps[g * 132 + kb + tg + 4]);
            a[3] = __float_as_uint(Ps[(g + 8) * 132 + kb + tg + 4]);
            bf[0] = __float_as_uint(Vs[(kb + tg) * 72 + n0 + g]);
            bf[1] = __float_as_uint(Vs[(kb + tg + 4) * 72 + n0 + g]);
            mma_tf32(dacc, a, bf);
        }
        float* Og = O + (size_t)b * 16 * 512 + h * 64;
        Og[(size_t)g * 512 + n0 + 2 * tg]           = dacc[0];
        Og[(size_t)g * 512 + n0 + 2 * tg + 1]       = dacc[1];
        Og[(size_t)(g + 8) * 512 + n0 + 2 * tg]     = dacc[2];
        Og[(size_t)(g + 8) * 512 + n0 + 2 * tg + 1] = dacc[3];
    }
}

// ---------------------------------------------------------------------------
extern "C" void kernel_launch(void* const* d_in, const int* in_sizes, int n_in,
                              void* d_out, int out_size)
{
    const float* x  = (const float*)d_in[0];
    const float* l  = (const float*)d_in[1];
    const float* Wq = (const float*)d_in[2];
    const float* Wk = (const float*)d_in[3];
    const float* Wv = (const float*)d_in[4];
    const float* Wo = (const float*)d_in[5];
    const float* bo = (const float*)d_in[6];
    float* out = (float*)d_out;

    float *Qp, *Kp, *Vp, *Ap, *Wt;
    cudaGetSymbolAddress((void**)&Qp, g_Q);
    cudaGetSymbolAddress((void**)&Kp, g_K);
    cudaGetSymbolAddress((void**)&Vp, g_V);
    cudaGetSymbolAddress((void**)&Ap, g_A);
    cudaGetSymbolAddress((void**)&Wt, g_Wt);
    const float* Wq_t = Wt + 0 * 512 * 512;
    const float* Wk_t = Wt + 1 * 512 * 512;
    const float* Wv_t = Wt + 2 * 512 * 512;
    const float* Wo_t = Wt + 3 * 512 * 512;

    const int smem_g1 = (2 * 128 * 36 + 2 * 1 * 64 * 36) * 4;   // 55296
    const int smem_g2 = (2 * 128 * 36 + 2 * 2 * 64 * 36) * 4;   // 73728
    const int smem_at = (16 * 76 + 128 * 76 + 128 * 72 + 16 * 132) * 4;  // 89088
    cudaFuncSetAttribute(gemm_kernel<1>, cudaFuncAttributeMaxDynamicSharedMemorySize, smem_g1);
    cudaFuncSetAttribute(gemm_kernel<2>, cudaFuncAttributeMaxDynamicSharedMemorySize, smem_g2);
    cudaFuncSetAttribute(attn_kernel, cudaFuncAttributeMaxDynamicSharedMemorySize, smem_at);

    dim3 blk(256);
    prep_w<<<1024, blk>>>(Wq, Wk, Wv, Wo);
    gemm_kernel<1><<<dim3(128, 8), blk, smem_g1>>>(x, Wq_t, nullptr, Qp, nullptr, nullptr, 0);
    gemm_kernel<2><<<dim3(1024, 8), blk, smem_g2>>>(l, Wk_t, Wv_t, Kp, Vp, nullptr, 1);
    attn_kernel<<<dim3(1024, 8), blk, smem_at>>>(Qp, Kp, Vp, Ap);
    gemm_kernel<1><<<dim3(128, 8), blk, smem_g1>>>(Ap, Wo_t, nullptr, out, nullptr, bo, 0);
}

// round 4
// speedup vs baseline: 2.2853x; 1.1134x over previous
#include <cuda_runtime.h>
#include <cstdint>
#include <cstddef>

// ---------------------------------------------------------------------------
// CrossAttentionDecoder: B=1024 (8*128), n_tok=16, num_latents=128, d=512,
// heads=8, dh=64.  Mask: batch b attends only to latents j <= (b % 128).
//
// Legacy mma.sync tf32 path (tcgen05 unavailable: harness compiles via
// non-'a' virtual arch).  All GEMM operands pre-packed into fragment order:
//   A-frag layout:  [mTile][kk(64)][mt(8)][lane(32)][4]   (m16n8k8 A frag)
//   W-frag layout:  [nt8][kk(64)][lane(32)][2]            (m16n8k8 B frag)
// GEMM: BM=128, BN=256, K-chunk 32, 512 threads, cp.async double buffer,
// grid ordered n-fastest so the 4 CTAs sharing an A tile hit L2.
// ---------------------------------------------------------------------------

#define DIMK 512

__device__ float g_Q[1024 * 16 * 512];          //  32 MB (row-major)
__device__ float g_K[1024 * 128 * 512];         // 256 MB (row-major)
__device__ float g_V[1024 * 128 * 512];         // 256 MB (row-major)
__device__ float g_Xf[128ull * 64 * 8 * 32 * 4];    // packed x
__device__ float g_Lf[1024ull * 64 * 8 * 32 * 4];   // packed l (256 MB)
__device__ float g_Af[128ull * 64 * 8 * 32 * 4];    // packed attn output
__device__ float g_Wqf[64 * 64 * 32 * 2];
__device__ float g_Wkvf[128 * 64 * 32 * 2];     // nt8 0..63 = Wk, 64..127 = Wv
__device__ float g_Wof[64 * 64 * 32 * 2];

// ---------------- helpers ---------------------------------------------------
__device__ __forceinline__ float to_tf32(float x) {
    uint32_t u; asm("cvt.rna.tf32.f32 %0, %1;" : "=r"(u) : "f"(x));
    return __uint_as_float(u);
}

__device__ __forceinline__ void mma_tf32(float* d, const uint32_t* a, const uint32_t* b) {
    asm volatile(
        "mma.sync.aligned.m16n8k8.row.col.f32.tf32.tf32.f32 "
        "{%0,%1,%2,%3}, {%4,%5,%6,%7}, {%8,%9}, {%0,%1,%2,%3};\n"
        : "+f"(d[0]), "+f"(d[1]), "+f"(d[2]), "+f"(d[3])
        : "r"(a[0]), "r"(a[1]), "r"(a[2]), "r"(a[3]),
          "r"(b[0]), "r"(b[1]));
}

__device__ __forceinline__ void cp_async16(uint32_t sdst, const void* gsrc) {
    asm volatile("cp.async.ca.shared.global [%0], [%1], 16;\n" :: "r"(sdst), "l"(gsrc));
}

__device__ __forceinline__ uint32_t smem_u32(const void* p) {
    uint32_t a;
    asm("{ .reg .u64 t; cvta.to.shared.u64 t, %1; cvt.u32.u64 %0, t; }" : "=r"(a) : "l"(p));
    return a;
}

// packed-A index for value at global row R, col c
__device__ __forceinline__ size_t pidx(int R, int c) {
    int mA = R >> 7, loc = R & 127, mt = loc >> 4, rr = loc & 15;
    int gp = rr & 7, abot = rr >> 3;
    int kk = c >> 3, kb = c & 7, tgp = kb & 3, ahi = kb >> 2;
    return ((((size_t)mA * 64 + kk) * 8 + mt) * 32 + (gp * 4 + tgp)) * 4 + (abot + 2 * ahi);
}

// ---------------------------------------------------------------------------
// prep_w: tf32-round + fragment-pack the four weight matrices.
// One thread per (nv, kk, lane) -> one float2 b-fragment pair.
// ---------------------------------------------------------------------------
__global__ __launch_bounds__(256)
void prep_w(const float* __restrict__ Wq, const float* __restrict__ Wk,
            const float* __restrict__ Wv, const float* __restrict__ Wo)
{
    int gid = blockIdx.x * 256 + threadIdx.x;        // 2048 blocks -> 524288
    int lane = gid & 31, kk = (gid >> 5) & 63, nv = gid >> 11;
    int gq = lane >> 2, tg = lane & 3;
    const float* W; float* dst; int sn, dn;
    if (nv < 64)       { W = Wq; dst = g_Wqf;  sn = nv;       dn = nv; }
    else if (nv < 128) { W = Wk; dst = g_Wkvf; sn = nv - 64;  dn = nv - 64; }
    else if (nv < 192) { W = Wv; dst = g_Wkvf; sn = nv - 128; dn = nv - 128 + 64; }
    else               { W = Wo; dst = g_Wof;  sn = nv - 192; dn = nv - 192; }
    float v0 = to_tf32(W[(size_t)(sn * 8 + gq) * DIMK + kk * 8 + tg]);
    float v1 = to_tf32(W[(size_t)(sn * 8 + gq) * DIMK + kk * 8 + tg + 4]);
    *(float2*)(dst + ((size_t)(dn * 64 + kk) * 32 + lane) * 2) = make_float2(v0, v1);
}

// ---------------------------------------------------------------------------
// prep_a: tf32-round + fragment-pack x (mAi<128) and l (mAi>=128, mask-skipped).
// One thread per a-fragment (4 floats) -> 4 scattered LDG + 1 STG.128.
// ---------------------------------------------------------------------------
__global__ __launch_bounds__(256)
void prep_a(const float* __restrict__ x, const float* __restrict__ l)
{
    size_t gid = (size_t)blockIdx.x * 256 + threadIdx.x;   // 73728 blocks
    int lane = (int)(gid & 31), mt = (int)((gid >> 5) & 7), kk = (int)((gid >> 8) & 63);
    int mAi = (int)(gid >> 14);
    int gp = lane >> 2, tgp = lane & 3;
    const float* src; float* dst; int mA;
    if (mAi < 128) { src = x; dst = g_Xf; mA = mAi; }
    else {
        src = l; dst = g_Lf; mA = mAi - 128;
        int valid = (mA & 127) + 1;
        if (mt * 16 >= valid) return;    // dead rows: never consumed by mma
    }
    size_t R0 = (size_t)mA * 128 + mt * 16 + gp, R1 = R0 + 8;
    int c0 = kk * 8 + tgp;
    float4 v;
    v.x = to_tf32(src[R0 * DIMK + c0]);
    v.y = to_tf32(src[R1 * DIMK + c0]);
    v.z = to_tf32(src[R0 * DIMK + c0 + 4]);
    v.w = to_tf32(src[R1 * DIMK + c0 + 4]);
    *(float4*)(dst + ((((size_t)mA * 64 + kk) * 8 + mt) * 32 + lane) * 4) = v;
}

// ---------------------------------------------------------------------------
// gemm_f: C[m*128+r][c] = sum_k A[r][k] * W[c][k]  over packed operands.
// BM=128, BN=256 (virtual cols across C0|C1), 512 threads = 16 warps (4m x 4n),
// warp tile 32m x 64n.  cp.async double buffer, n-block fastest in grid.
// masked: valid rows = (m & 127)+1; compute skipped at 32-row warp grain,
// stores masked per row.
// ---------------------------------------------------------------------------
__global__ __launch_bounds__(512, 1)
void gemm_f(const float* __restrict__ Ap, const float* __restrict__ Wf,
            float* __restrict__ C0, float* __restrict__ C1,
            const float* __restrict__ bias, int masked, int nbc)
{
    extern __shared__ __align__(16) float sm[];
    float* As = sm;            // [2][4096]  (16KB per stage)
    float* Ws = sm + 8192;     // [2][8192]  (32KB per stage)
    const uint32_t sbA = smem_u32(sm);
    const uint32_t sbW = sbA + 8192 * 4;

    const int bx = blockIdx.x;
    const int m = bx / nbc, nb = bx - m * nbc;
    const int colbase = nb * 256;
    const int valid = masked ? (m & 127) + 1 : 128;
    const int tid = threadIdx.x;
    const int warp = tid >> 5, lane = tid & 31;
    const int wm = warp >> 2, wn = warp & 3;
    const int g = lane >> 2, tg = lane & 3;
    const bool active = (wm * 32) < valid;

    const float* Abase = Ap + (size_t)m * 65536;
    const float* Wbase = Wf + (size_t)(colbase >> 3) * 4096;

    float acc[2][8][4];
    #pragma unroll
    for (int i = 0; i < 2; i++)
        #pragma unroll
        for (int j = 0; j < 8; j++)
            #pragma unroll
            for (int c = 0; c < 4; c++) acc[i][j][c] = 0.f;

    auto do_stage = [&](int it) {
        const int s = it & 1;
        uint32_t Ad = sbA + s * 16384;
        uint32_t Wd = sbW + s * 32768;
        const float* Asrc = Abase + (size_t)it * 4096;
        cp_async16(Ad + tid * 16, Asrc + tid * 4);
        cp_async16(Ad + (tid + 512) * 16, Asrc + (tid + 512) * 4);
        #pragma unroll
        for (int i = 0; i < 4; i++) {
            int j = tid + i * 512;               // 0..2047
            int nt8l = j >> 6, w = j & 63;
            cp_async16(Wd + (uint32_t)(nt8l * 1024 + w * 16),
                       Wbase + (size_t)nt8l * 4096 + it * 256 + w * 4);
        }
        asm volatile("cp.async.commit_group;\n" ::: "memory");
    };

    do_stage(0);
    do_stage(1);

    for (int it = 0; it < 16; ++it) {
        if (it < 15) asm volatile("cp.async.wait_group 1;\n" ::: "memory");
        else         asm volatile("cp.async.wait_group 0;\n" ::: "memory");
        __syncthreads();
        if (active) {
            const float* Ac = As + (it & 1) * 4096;
            const float* Wc = Ws + (it & 1) * 8192;
            #pragma unroll
            for (int kk = 0; kk < 4; ++kk) {
                const float* Ab = Ac + kk * 1024;
                uint4 a0 = *(const uint4*)(Ab + (wm * 2 + 0) * 128 + lane * 4);
                uint4 a1 = *(const uint4*)(Ab + (wm * 2 + 1) * 128 + lane * 4);
                uint32_t au0[4] = {a0.x, a0.y, a0.z, a0.w};
                uint32_t au1[4] = {a1.x, a1.y, a1.z, a1.w};
                #pragma unroll
                for (int nt = 0; nt < 8; ++nt) {
                    int nt8l = wn * 8 + nt;
                    float2 bv = *(const float2*)(Wc + nt8l * 256 + kk * 64 + lane * 2);
                    uint32_t bu[2] = {__float_as_uint(bv.x), __float_as_uint(bv.y)};
                    mma_tf32(acc[0][nt], au0, bu);
                    mma_tf32(acc[1][nt], au1, bu);
                }
            }
        }
        __syncthreads();
        if (it + 2 < 16) do_stage(it + 2);
    }

    if (!active) return;
    #pragma unroll
    for (int mt = 0; mt < 2; ++mt) {
        int r0 = wm * 32 + mt * 16 + g;
        int r1 = r0 + 8;
        #pragma unroll
        for (int nt = 0; nt < 8; ++nt) {
            int c = colbase + wn * 64 + nt * 8 + 2 * tg;
            int cr = c & 511;
            float* C = (c < 512) ? C0 : C1;
            float b0 = 0.f, b1 = 0.f;
            if (bias) { b0 = bias[cr]; b1 = bias[cr + 1]; }
            if (r0 < valid)
                *(float2*)(C + ((size_t)m * 128 + r0) * DIMK + cr) =
                    make_float2(acc[mt][nt][0] + b0, acc[mt][nt][1] + b1);
            if (r1 < valid)
                *(float2*)(C + ((size_t)m * 128 + r1) * DIMK + cr) =
                    make_float2(acc[mt][nt][2] + b0, acc[mt][nt][3] + b1);
        }
    }
}

// ---------------------------------------------------------------------------
// Attention: one CTA per (b,h), legacy tensor-core mma (R1-verified layout).
// Output written tf32-rounded directly into packed-fragment g_Af for O-proj.
// ---------------------------------------------------------------------------
__global__ __launch_bounds__(256)
void attn_kernel(const float* __restrict__ Q, const float* __restrict__ K,
                 const float* __restrict__ V)
{
    const int b = blockIdx.x, h = blockIdx.y;
    const int r = b & 127, nj = r + 1;
    const int njp8 = (nj + 7) & ~7;

    extern __shared__ float sm[];
    float* Qs = sm;                 // 16 x 76
    float* Ks = Qs + 16 * 76;       // 128 x 76
    float* Vs = Ks + 128 * 76;      // 128 x 72
    float* Ps = Vs + 128 * 72;      // 16 x 132

    const int tid = threadIdx.x;
    const int warp = tid >> 5, lane = tid & 31;
    const int g = lane >> 2, tg = lane & 3;

    {
        int row = tid >> 4, c4 = (tid & 15) << 2;
        float4 v = *(const float4*)(Q + (size_t)b * 16 * 512 + (size_t)row * 512 + h * 64 + c4);
        float* d = Qs + row * 76 + c4;
        d[0] = to_tf32(v.x); d[1] = to_tf32(v.y); d[2] = to_tf32(v.z); d[3] = to_tf32(v.w);
    }
    const float* Kg = K + (size_t)b * 128 * 512 + h * 64;
    const float* Vg = V + (size_t)b * 128 * 512 + h * 64;
    for (int i = tid; i < nj * 16; i += 256) {
        int row = i >> 4, c4 = (i & 15) << 2;
        float4 kv = *(const float4*)(Kg + (size_t)row * 512 + c4);
        float4 vv = *(const float4*)(Vg + (size_t)row * 512 + c4);
        float* kd = Ks + row * 76 + c4;
        kd[0] = to_tf32(kv.x); kd[1] = to_tf32(kv.y); kd[2] = to_tf32(kv.z); kd[3] = to_tf32(kv.w);
        float* vd = Vs + row * 72 + c4;
        vd[0] = to_tf32(vv.x); vd[1] = to_tf32(vv.y); vd[2] = to_tf32(vv.z); vd[3] = to_tf32(vv.w);
    }
    __syncthreads();

    #pragma unroll
    for (int t = 0; t < 2; t++) {
        int n0 = warp * 8 + t * 64;
        if (n0 < njp8) {
            float dacc[4] = {0.f, 0.f, 0.f, 0.f};
            #pragma unroll
            for (int kb = 0; kb < 64; kb += 8) {
                uint32_t a[4], bf[2];
                a[0] = __float_as_uint(Qs[g * 76 + kb + tg]);
                a[1] = __float_as_uint(Qs[(g + 8) * 76 + kb + tg]);
                a[2] = __float_as_uint(Qs[g * 76 + kb + tg + 4]);
                a[3] = __float_as_uint(Qs[(g + 8) * 76 + kb + tg + 4]);
                bf[0] = __float_as_uint(Ks[(n0 + g) * 76 + kb + tg]);
                bf[1] = __float_as_uint(Ks[(n0 + g) * 76 + kb + tg + 4]);
                mma_tf32(dacc, a, bf);
            }
            Ps[g * 132 + n0 + 2 * tg]           = dacc[0] * 0.125f;
            Ps[g * 132 + n0 + 2 * tg + 1]       = dacc[1] * 0.125f;
            Ps[(g + 8) * 132 + n0 + 2 * tg]     = dacc[2] * 0.125f;
            Ps[(g + 8) * 132 + n0 + 2 * tg + 1] = dacc[3] * 0.125f;
        }
    }
    __syncthreads();

    #pragma unroll
    for (int rr = 0; rr < 2; rr++) {
        int row = warp * 2 + rr;
        float* p = Ps + row * 132;
        float mx = -1e30f;
        for (int j = lane; j < nj; j += 32) mx = fmaxf(mx, p[j]);
        #pragma unroll
        for (int o = 16; o; o >>= 1) mx = fmaxf(mx, __shfl_xor_sync(0xffffffffu, mx, o));
        float e[4]; int cnt = 0; float s = 0.f;
        for (int j = lane; j < nj; j += 32) { float ev = __expf(p[j] - mx); e[cnt++] = ev; s += ev; }
        #pragma unroll
        for (int o = 16; o; o >>= 1) s += __shfl_xor_sync(0xffffffffu, s, o);
        float inv = 1.f / s;
        cnt = 0;
        for (int j = lane; j < njp8; j += 32) {
            float val = (j < nj) ? e[cnt++] * inv : 0.f;
            p[j] = to_tf32(val);
        }
    }
    __syncthreads();

    {
        int n0 = warp * 8;
        float dacc[4] = {0.f, 0.f, 0.f, 0.f};
        for (int kb = 0; kb < njp8; kb += 8) {
            uint32_t a[4], bf[2];
            a[0] = __float_as_uint(Ps[g * 132 + kb + tg]);
            a[1] = __float_as_uint(Ps[(g + 8) * 132 + kb + tg]);
            a[2] = __float_as_uint(Ps[g * 132 + kb + tg + 4]);
            a[3] = __float_as_uint(Ps[(g + 8) * 132 + kb + tg + 4]);
            bf[0] = __float_as_uint(Vs[(kb + tg) * 72 + n0 + g]);
            bf[1] = __float_as_uint(Vs[(kb + tg + 4) * 72 + n0 + g]);
            mma_tf32(dacc, a, bf);
        }
        int R0 = b * 16 + g;
        int c0 = h * 64 + n0 + 2 * tg;
        g_Af[pidx(R0, c0)]         = to_tf32(dacc[0]);
        g_Af[pidx(R0, c0 + 1)]     = to_tf32(dacc[1]);
        g_Af[pidx(R0 + 8, c0)]     = to_tf32(dacc[2]);
        g_Af[pidx(R0 + 8, c0 + 1)] = to_tf32(dacc[3]);
    }
}

// ---------------------------------------------------------------------------
extern "C" void kernel_launch(void* const* d_in, const int* in_sizes, int n_in,
                              void* d_out, int out_size)
{
    const float* x  = (const float*)d_in[0];
    const float* l  = (const float*)d_in[1];
    const float* Wq = (const float*)d_in[2];
    const float* Wk = (const float*)d_in[3];
    const float* Wv = (const float*)d_in[4];
    const float* Wo = (const float*)d_in[5];
    const float* bo = (const float*)d_in[6];
    float* out = (float*)d_out;

    float *Qp, *Kp, *Vp, *Xf, *Lf, *Af, *Wqf, *Wkvf, *Wof;
    cudaGetSymbolAddress((void**)&Qp,  g_Q);
    cudaGetSymbolAddress((void**)&Kp,  g_K);
    cudaGetSymbolAddress((void**)&Vp,  g_V);
    cudaGetSymbolAddress((void**)&Xf,  g_Xf);
    cudaGetSymbolAddress((void**)&Lf,  g_Lf);
    cudaGetSymbolAddress((void**)&Af,  g_Af);
    cudaGetSymbolAddress((void**)&Wqf, g_Wqf);
    cudaGetSymbolAddress((void**)&Wkvf, g_Wkvf);
    cudaGetSymbolAddress((void**)&Wof, g_Wof);

    const int smem_g  = (8192 + 16384) * 4;   // 98304
    const int smem_at = (16 * 76 + 128 * 76 + 128 * 72 + 16 * 132) * 4;
    cudaFuncSetAttribute(gemm_f, cudaFuncAttributeMaxDynamicSharedMemorySize, smem_g);
    cudaFuncSetAttribute(attn_kernel, cudaFuncAttributeMaxDynamicSharedMemorySize, smem_at);

    prep_w<<<2048, 256>>>(Wq, Wk, Wv, Wo);
    prep_a<<<73728, 256>>>(x, l);
    // Q projection: 128 m-tiles x 2 n-blocks (n fastest)
    gemm_f<<<256, 512, smem_g>>>(Xf, Wqf, Qp, nullptr, nullptr, 0, 2);
    // K,V projections: 1024 m-tiles x 4 n-blocks over virtual N=1024
    gemm_f<<<4096, 512, smem_g>>>(Lf, Wkvf, Kp, Vp, nullptr, 1, 4);
    // attention -> packed g_Af
    attn_kernel<<<dim3(1024, 8), 256, smem_at>>>(Qp, Kp, Vp);
    // output projection + bias
    gemm_f<<<256, 512, smem_g>>>(Af, Wof, out, nullptr, bo, 0, 2);
}

// round 5
// speedup vs baseline: 2.7085x; 1.1852x over previous
#include <cuda_runtime.h>
#include <cstdint>
#include <cstddef>

// ---------------------------------------------------------------------------
// CrossAttentionDecoder: B=1024 (8*128), n_tok=16, num_latents=128, d=512,
// heads=8, dh=64.  Mask: batch b attends only to latents j <= (b % 128).
//
// Projection-absorbed formulation (K,V never materialized):
//   scores[b,h] = (q[b,h] @ Wk_h) @ l[b]^T      (qk: 16x512)
//   out[b,h]    = (P @ l[b]) @ Wv_h^T           (pl: 16x512)
// Pipeline:
//   1. prep_w: fragment-pack Wq, Wv, Wo (R4 style) + Wk transposed pack
//   2. prep_a: fragment-pack x
//   3. gemm_f: q = x @ Wq^T            (row-major g_Q)
//   4. fattn : per (b, head-pair) fused qk/scores/softmax/pl/ov -> packed g_Af
//   5. gemm_f: out = A @ Wo^T + bo
// ---------------------------------------------------------------------------

#define DIMK 512

__device__ float g_Q[1024 * 16 * 512];              // 32 MB row-major q
__device__ float g_Xf[128ull * 64 * 8 * 32 * 4];    // packed x
__device__ float g_Af[128ull * 64 * 8 * 32 * 4];    // packed attn output
__device__ float g_Wqf[64 * 64 * 32 * 2];
__device__ float g_Wvf[64 * 64 * 32 * 2];
__device__ float g_Wof[64 * 64 * 32 * 2];
__device__ float g_Wkf[8 * 64 * 8 * 32 * 2];        // transposed pack for qk

// ---------------- helpers ---------------------------------------------------
__device__ __forceinline__ float to_tf32(float x) {
    uint32_t u; asm("cvt.rna.tf32.f32 %0, %1;" : "=r"(u) : "f"(x));
    return __uint_as_float(u);
}
__device__ __forceinline__ uint32_t f2u(float x) { return __float_as_uint(x); }

__device__ __forceinline__ void mma_tf32(float* d, const uint32_t* a, const uint32_t* b) {
    asm volatile(
        "mma.sync.aligned.m16n8k8.row.col.f32.tf32.tf32.f32 "
        "{%0,%1,%2,%3}, {%4,%5,%6,%7}, {%8,%9}, {%0,%1,%2,%3};\n"
        : "+f"(d[0]), "+f"(d[1]), "+f"(d[2]), "+f"(d[3])
        : "r"(a[0]), "r"(a[1]), "r"(a[2]), "r"(a[3]),
          "r"(b[0]), "r"(b[1]));
}

__device__ __forceinline__ void cp_async16(uint32_t sdst, const void* gsrc) {
    asm volatile("cp.async.ca.shared.global [%0], [%1], 16;\n" :: "r"(sdst), "l"(gsrc));
}

__device__ __forceinline__ uint32_t smem_u32(const void* p) {
    uint32_t a;
    asm("{ .reg .u64 t; cvta.to.shared.u64 t, %1; cvt.u32.u64 %0, t; }" : "=r"(a) : "l"(p));
    return a;
}

// packed-A index for value at global row R, col c  (m16n8k8 A-fragment order)
__device__ __forceinline__ size_t pidx(int R, int c) {
    int mA = R >> 7, loc = R & 127, mt = loc >> 4, rr = loc & 15;
    int gp = rr & 7, abot = rr >> 3;
    int kk = c >> 3, kb = c & 7, tgp = kb & 3, ahi = kb >> 2;
    return ((((size_t)mA * 64 + kk) * 8 + mt) * 32 + (gp * 4 + tgp)) * 4 + (abot + 2 * ahi);
}

// ---------------------------------------------------------------------------
// prep_w: fragment-pack Wq, Wv, Wo (B[n][k] = W[n][k]) and Wk transposed
// (B[n][k] = Wk[h*64+k][n]) for the in-attention qk GEMM.
// ---------------------------------------------------------------------------
__global__ __launch_bounds__(256)
void prep_w(const float* __restrict__ Wq, const float* __restrict__ Wk,
            const float* __restrict__ Wv, const float* __restrict__ Wo)
{
    int gid = blockIdx.x * 256 + threadIdx.x;        // 2048 blocks -> 524288
    int lane = gid & 31, kk = (gid >> 5) & 63, nv = gid >> 11;   // nv 0..255
    int g = lane >> 2, tg = lane & 3;
    if (nv < 192) {
        const float* W; float* dst; int dn;
        if (nv < 64)       { W = Wq; dst = g_Wqf; dn = nv; }
        else if (nv < 128) { W = Wv; dst = g_Wvf; dn = nv - 64; }
        else               { W = Wo; dst = g_Wof; dn = nv - 128; }
        float v0 = to_tf32(W[(size_t)(dn * 8 + g) * DIMK + kk * 8 + tg]);
        float v1 = to_tf32(W[(size_t)(dn * 8 + g) * DIMK + kk * 8 + tg + 4]);
        *(float2*)(dst + ((size_t)(dn * 64 + kk) * 32 + lane) * 2) = make_float2(v0, v1);
    } else {
        int t = nv - 192;            // 0..63
        int h = t >> 3, ks = t & 7;
        int ntg = kk;                // qk col-tile 0..63
        float v0 = to_tf32(Wk[(size_t)(h * 64 + ks * 8 + tg) * DIMK + ntg * 8 + g]);
        float v1 = to_tf32(Wk[(size_t)(h * 64 + ks * 8 + tg + 4) * DIMK + ntg * 8 + g]);
        *(float2*)(g_Wkf + ((size_t)((h * 64 + ntg) * 8 + ks) * 32 + lane) * 2) =
            make_float2(v0, v1);
    }
}

// ---------------------------------------------------------------------------
// prep_a: tf32-round + fragment-pack x.
// ---------------------------------------------------------------------------
__global__ __launch_bounds__(256)
void prep_a(const float* __restrict__ x)
{
    size_t gid = (size_t)blockIdx.x * 256 + threadIdx.x;   // 8192 blocks
    int lane = (int)(gid & 31), mt = (int)((gid >> 5) & 7), kk = (int)((gid >> 8) & 63);
    int mA = (int)(gid >> 14);      // 0..127
    int gp = lane >> 2, tgp = lane & 3;
    size_t R0 = (size_t)mA * 128 + mt * 16 + gp, R1 = R0 + 8;
    int c0 = kk * 8 + tgp;
    float4 v;
    v.x = to_tf32(x[R0 * DIMK + c0]);
    v.y = to_tf32(x[R1 * DIMK + c0]);
    v.z = to_tf32(x[R0 * DIMK + c0 + 4]);
    v.w = to_tf32(x[R1 * DIMK + c0 + 4]);
    *(float4*)(g_Xf + ((((size_t)mA * 64 + kk) * 8 + mt) * 32 + lane) * 4) = v;
}

// ---------------------------------------------------------------------------
// gemm_f (unchanged from R4): C = A_packed @ W_packed^T (+bias), BM=128 BN=256.
// ---------------------------------------------------------------------------
__global__ __launch_bounds__(512, 1)
void gemm_f(const float* __restrict__ Ap, const float* __restrict__ Wf,
            float* __restrict__ C0, float* __restrict__ C1,
            const float* __restrict__ bias, int masked, int nbc)
{
    extern __shared__ __align__(16) float sm[];
    float* As = sm;            // [2][4096]
    float* Ws = sm + 8192;     // [2][8192]
    const uint32_t sbA = smem_u32(sm);
    const uint32_t sbW = sbA + 8192 * 4;

    const int bx = blockIdx.x;
    const int m = bx / nbc, nb = bx - m * nbc;
    const int colbase = nb * 256;
    const int valid = masked ? (m & 127) + 1 : 128;
    const int tid = threadIdx.x;
    const int warp = tid >> 5, lane = tid & 31;
    const int wm = warp >> 2, wn = warp & 3;
    const int g = lane >> 2, tg = lane & 3;
    const bool active = (wm * 32) < valid;

    const float* Abase = Ap + (size_t)m * 65536;
    const float* Wbase = Wf + (size_t)(colbase >> 3) * 4096;

    float acc[2][8][4];
    #pragma unroll
    for (int i = 0; i < 2; i++)
        #pragma unroll
        for (int j = 0; j < 8; j++)
            #pragma unroll
            for (int c = 0; c < 4; c++) acc[i][j][c] = 0.f;

    auto do_stage = [&](int it) {
        const int s = it & 1;
        uint32_t Ad = sbA + s * 16384;
        uint32_t Wd = sbW + s * 32768;
        const float* Asrc = Abase + (size_t)it * 4096;
        cp_async16(Ad + tid * 16, Asrc + tid * 4);
        cp_async16(Ad + (tid + 512) * 16, Asrc + (tid + 512) * 4);
        #pragma unroll
        for (int i = 0; i < 4; i++) {
            int j = tid + i * 512;
            int nt8l = j >> 6, w2 = j & 63;
            cp_async16(Wd + (uint32_t)(nt8l * 1024 + w2 * 16),
                       Wbase + (size_t)nt8l * 4096 + it * 256 + w2 * 4);
        }
        asm volatile("cp.async.commit_group;\n" ::: "memory");
    };

    do_stage(0);
    do_stage(1);

    for (int it = 0; it < 16; ++it) {
        if (it < 15) asm volatile("cp.async.wait_group 1;\n" ::: "memory");
        else         asm volatile("cp.async.wait_group 0;\n" ::: "memory");
        __syncthreads();
        if (active) {
            const float* Ac = As + (it & 1) * 4096;
            const float* Wc = Ws + (it & 1) * 8192;
            #pragma unroll
            for (int kk = 0; kk < 4; ++kk) {
                const float* Ab = Ac + kk * 1024;
                uint4 a0 = *(const uint4*)(Ab + (wm * 2 + 0) * 128 + lane * 4);
                uint4 a1 = *(const uint4*)(Ab + (wm * 2 + 1) * 128 + lane * 4);
                uint32_t au0[4] = {a0.x, a0.y, a0.z, a0.w};
                uint32_t au1[4] = {a1.x, a1.y, a1.z, a1.w};
                #pragma unroll
                for (int nt = 0; nt < 8; ++nt) {
                    int nt8l = wn * 8 + nt;
                    float2 bv = *(const float2*)(Wc + nt8l * 256 + kk * 64 + lane * 2);
                    uint32_t bu[2] = {f2u(bv.x), f2u(bv.y)};
                    mma_tf32(acc[0][nt], au0, bu);
                    mma_tf32(acc[1][nt], au1, bu);
                }
            }
        }
        __syncthreads();
        if (it + 2 < 16) do_stage(it + 2);
    }

    if (!active) return;
    #pragma unroll
    for (int mt = 0; mt < 2; ++mt) {
        int r0 = wm * 32 + mt * 16 + g;
        int r1 = r0 + 8;
        #pragma unroll
        for (int nt = 0; nt < 8; ++nt) {
            int c = colbase + wn * 64 + nt * 8 + 2 * tg;
            int cr = c & 511;
            float* C = (c < 512) ? C0 : C1;
            float b0 = 0.f, b1 = 0.f;
            if (bias) { b0 = bias[cr]; b1 = bias[cr + 1]; }
            if (r0 < valid)
                *(float2*)(C + ((size_t)m * 128 + r0) * DIMK + cr) =
                    make_float2(acc[mt][nt][0] + b0, acc[mt][nt][1] + b1);
            if (r1 < valid)
                *(float2*)(C + ((size_t)m * 128 + r1) * DIMK + cr) =
                    make_float2(acc[mt][nt][2] + b0, acc[mt][nt][3] + b1);
        }
    }
}

// ---------------------------------------------------------------------------
// fattn: fused qk -> scores -> softmax -> pl -> ov.  One CTA per (b, head-pair).
// SMEM (floats): q2[2][16][68] | sc2[2][16][132] | qk2/pl2[2][16][516] |
//                lbuf[2][32][516]      total 55936 floats = 218.5 KB
// ---------------------------------------------------------------------------
#define FSM_Q  0
#define FSM_SC 2176
#define FSM_QK 6400
#define FSM_L  22912
#define FSM_TOT 55936

__global__ __launch_bounds__(256, 1)
void fattn(const float* __restrict__ Q, const float* __restrict__ l,
           const float* __restrict__ Wkf, const float* __restrict__ Wvf)
{
    extern __shared__ __align__(16) float sm[];
    const uint32_t sb = smem_u32(sm);

    const int bx = blockIdx.x;
    const int b = bx >> 2, hp = bx & 3;
    const int h0 = hp * 2;
    const int nj = (b & 127) + 1;
    const int nchunks = (nj + 31) >> 5;
    const int njc = nchunks << 5;

    const int tid = threadIdx.x;
    const int w = tid >> 5, lane = tid & 31;
    const int g = lane >> 2, tg = lane & 3;

    float* q2  = sm + FSM_Q;
    float* sc2 = sm + FSM_SC;
    float* qk2 = sm + FSM_QK;
    float* lb  = sm + FSM_L;

    // ---- load q for both heads (tf32) ----
    #pragma unroll
    for (int i = 0; i < 2; i++) {
        int idx = tid + i * 256;                 // 0..511
        int hh = idx >> 8, rr = (idx >> 4) & 15, c4 = (idx & 15) * 4;
        float4 v = *(const float4*)(Q + (size_t)(b * 16 + rr) * 512 + (h0 + hh) * 64 + c4);
        float* d = q2 + hh * (16 * 68) + rr * 68 + c4;
        d[0] = to_tf32(v.x); d[1] = to_tf32(v.y); d[2] = to_tf32(v.z); d[3] = to_tf32(v.w);
    }
    __syncthreads();

    // ---- phase A: qk[hh] = q[hh] @ Wk_h (B from packed g_Wkf) ----
    #pragma unroll
    for (int hh = 0; hh < 2; hh++) {
        const int h = h0 + hh;
        const float* qs = q2 + hh * (16 * 68);
        float acc[8][4];
        #pragma unroll
        for (int nt = 0; nt < 8; nt++)
            #pragma unroll
            for (int c = 0; c < 4; c++) acc[nt][c] = 0.f;
        #pragma unroll
        for (int ks = 0; ks < 8; ks++) {
            uint32_t a[4];
            a[0] = f2u(qs[g * 68 + ks * 8 + tg]);
            a[1] = f2u(qs[(g + 8) * 68 + ks * 8 + tg]);
            a[2] = f2u(qs[g * 68 + ks * 8 + tg + 4]);
            a[3] = f2u(qs[(g + 8) * 68 + ks * 8 + tg + 4]);
            #pragma unroll
            for (int nt = 0; nt < 8; nt++) {
                float2 bv = *(const float2*)(Wkf +
                    ((size_t)((h * 64 + w * 8 + nt) * 8 + ks) * 32 + lane) * 2);
                uint32_t bu[2] = {f2u(bv.x), f2u(bv.y)};
                mma_tf32(acc[nt], a, bu);
            }
        }
        float* qd = qk2 + hh * (16 * 516);
        #pragma unroll
        for (int nt = 0; nt < 8; nt++) {
            int c = w * 64 + nt * 8 + 2 * tg;
            qd[g * 516 + c]         = to_tf32(acc[nt][0]);
            qd[g * 516 + c + 1]     = to_tf32(acc[nt][1]);
            qd[(g + 8) * 516 + c]     = to_tf32(acc[nt][2]);
            qd[(g + 8) * 516 + c + 1] = to_tf32(acc[nt][3]);
        }
    }
    __syncthreads();

    // ---- l-chunk staging (32 rows x 512 @ stride 516, zero pad rows) ----
    auto stage = [&](int ci) {
        const int s = ci & 1;
        const int j0 = ci << 5;
        uint32_t dstb = sb + (FSM_L + s * (32 * 516)) * 4;
        #pragma unroll
        for (int i = 0; i < 16; i++) {
            int idx = tid + i * 256;             // 0..4095
            int row = idx >> 7, cc = idx & 127;
            uint32_t d = dstb + (uint32_t)(row * 516 + cc * 4) * 4;
            if (j0 + row < nj) {
                cp_async16(d, l + ((size_t)(b * 128 + j0 + row) * 512 + cc * 4));
            } else {
                float* dp = lb + s * (32 * 516) + row * 516 + cc * 4;
                *(float4*)dp = make_float4(0.f, 0.f, 0.f, 0.f);
            }
        }
        asm volatile("cp.async.commit_group;\n" ::: "memory");
    };

    // ---- pass 1: scores = qk @ l^T ----
    stage(0);
    for (int ci = 0; ci < nchunks; ci++) {
        if (ci + 1 < nchunks) {
            stage(ci + 1);
            asm volatile("cp.async.wait_group 1;\n" ::: "memory");
        } else {
            asm volatile("cp.async.wait_group 0;\n" ::: "memory");
        }
        __syncthreads();
        {
            const int hh = w >> 2, nt = w & 3;
            const float* qs = qk2 + hh * (16 * 516);
            const float* lch = lb + (ci & 1) * (32 * 516);
            const int n0 = nt * 8;
            float acc[4] = {0.f, 0.f, 0.f, 0.f};
            #pragma unroll 8
            for (int ks = 0; ks < 64; ks++) {
                uint32_t a[4], bu[2];
                a[0] = f2u(qs[g * 516 + ks * 8 + tg]);
                a[1] = f2u(qs[(g + 8) * 516 + ks * 8 + tg]);
                a[2] = f2u(qs[g * 516 + ks * 8 + tg + 4]);
                a[3] = f2u(qs[(g + 8) * 516 + ks * 8 + tg + 4]);
                bu[0] = f2u(to_tf32(lch[(n0 + g) * 516 + ks * 8 + tg]));
                bu[1] = f2u(to_tf32(lch[(n0 + g) * 516 + ks * 8 + tg + 4]));
                mma_tf32(acc, a, bu);
            }
            float* sd = sc2 + hh * (16 * 132);
            const int jg = ci * 32 + n0 + 2 * tg;
            sd[g * 132 + jg]         = acc[0] * 0.125f;
            sd[g * 132 + jg + 1]     = acc[1] * 0.125f;
            sd[(g + 8) * 132 + jg]     = acc[2] * 0.125f;
            sd[(g + 8) * 132 + jg + 1] = acc[3] * 0.125f;
        }
        __syncthreads();
    }

    // ---- softmax (2 heads x 16 rows; 4 rows per warp) ----
    #pragma unroll
    for (int rr = 0; rr < 4; rr++) {
        int row = w * 4 + rr;
        int hh = row >> 4, i = row & 15;
        float* p = sc2 + hh * (16 * 132) + i * 132;
        float mx = -1e30f;
        for (int j = lane; j < nj; j += 32) mx = fmaxf(mx, p[j]);
        #pragma unroll
        for (int o = 16; o; o >>= 1) mx = fmaxf(mx, __shfl_xor_sync(0xffffffffu, mx, o));
        float e[4]; int cnt = 0; float s = 0.f;
        for (int j = lane; j < nj; j += 32) { float ev = __expf(p[j] - mx); e[cnt++] = ev; s += ev; }
        #pragma unroll
        for (int o = 16; o; o >>= 1) s += __shfl_xor_sync(0xffffffffu, s, o);
        float inv = 1.f / s;
        cnt = 0;
        for (int j = lane; j < njc; j += 32) {
            float val = (j < nj) ? e[cnt++] * inv : 0.f;
            p[j] = to_tf32(val);
        }
    }
    __syncthreads();

    // ---- pass 2: pl = P @ l (acc in regs, warp owns 64 cols, both heads) ----
    float pacc[2][8][4];
    #pragma unroll
    for (int hh = 0; hh < 2; hh++)
        #pragma unroll
        for (int nt = 0; nt < 8; nt++)
            #pragma unroll
            for (int c = 0; c < 4; c++) pacc[hh][nt][c] = 0.f;

    stage(0);
    for (int ci = 0; ci < nchunks; ci++) {
        if (ci + 1 < nchunks) {
            stage(ci + 1);
            asm volatile("cp.async.wait_group 1;\n" ::: "memory");
        } else {
            asm volatile("cp.async.wait_group 0;\n" ::: "memory");
        }
        __syncthreads();
        {
            const float* lch = lb + (ci & 1) * (32 * 516);
            #pragma unroll
            for (int hh = 0; hh < 2; hh++) {
                const float* sp = sc2 + hh * (16 * 132);
                #pragma unroll
                for (int ks = 0; ks < 4; ks++) {
                    const int jb = ks * 8;
                    uint32_t a[4];
                    a[0] = f2u(sp[g * 132 + ci * 32 + jb + tg]);
                    a[1] = f2u(sp[(g + 8) * 132 + ci * 32 + jb + tg]);
                    a[2] = f2u(sp[g * 132 + ci * 32 + jb + tg + 4]);
                    a[3] = f2u(sp[(g + 8) * 132 + ci * 32 + jb + tg + 4]);
                    #pragma unroll
                    for (int nt = 0; nt < 8; nt++) {
                        const int c = w * 64 + nt * 8 + g;
                        uint32_t bu[2];
                        bu[0] = f2u(to_tf32(lch[(jb + tg) * 516 + c]));
                        bu[1] = f2u(to_tf32(lch[(jb + tg + 4) * 516 + c]));
                        mma_tf32(pacc[hh][nt], a, bu);
                    }
                }
            }
        }
        __syncthreads();
    }

    // ---- store pl (tf32) into qk2 (qk dead) ----
    #pragma unroll
    for (int hh = 0; hh < 2; hh++) {
        float* qd = qk2 + hh * (16 * 516);
        #pragma unroll
        for (int nt = 0; nt < 8; nt++) {
            int c = w * 64 + nt * 8 + 2 * tg;
            qd[g * 516 + c]         = to_tf32(pacc[hh][nt][0]);
            qd[g * 516 + c + 1]     = to_tf32(pacc[hh][nt][1]);
            qd[(g + 8) * 516 + c]     = to_tf32(pacc[hh][nt][2]);
            qd[(g + 8) * 516 + c + 1] = to_tf32(pacc[hh][nt][3]);
        }
    }
    __syncthreads();

    // ---- phase E: out[hh] = pl[hh] @ Wv_h^T -> packed g_Af ----
    #pragma unroll
    for (int hh = 0; hh < 2; hh++) {
        const int h = h0 + hh;
        const float* ps = qk2 + hh * (16 * 516);
        float acc[4] = {0.f, 0.f, 0.f, 0.f};
        #pragma unroll 8
        for (int ks = 0; ks < 64; ks++) {
            uint32_t a[4];
            a[0] = f2u(ps[g * 516 + ks * 8 + tg]);
            a[1] = f2u(ps[(g + 8) * 516 + ks * 8 + tg]);
            a[2] = f2u(ps[g * 516 + ks * 8 + tg + 4]);
            a[3] = f2u(ps[(g + 8) * 516 + ks * 8 + tg + 4]);
            float2 bv = *(const float2*)(Wvf +
                ((size_t)((h * 8 + w) * 64 + ks) * 32 + lane) * 2);
            uint32_t bu[2] = {f2u(bv.x), f2u(bv.y)};
            mma_tf32(acc, a, bu);
        }
        int R0 = b * 16 + g;
        int c0 = h * 64 + w * 8 + 2 * tg;
        g_Af[pidx(R0, c0)]         = to_tf32(acc[0]);
        g_Af[pidx(R0, c0 + 1)]     = to_tf32(acc[1]);
        g_Af[pidx(R0 + 8, c0)]     = to_tf32(acc[2]);
        g_Af[pidx(R0 + 8, c0 + 1)] = to_tf32(acc[3]);
    }
}

// ---------------------------------------------------------------------------
extern "C" void kernel_launch(void* const* d_in, const int* in_sizes, int n_in,
                              void* d_out, int out_size)
{
    const float* x  = (const float*)d_in[0];
    const float* l  = (const float*)d_in[1];
    const float* Wq = (const float*)d_in[2];
    const float* Wk = (const float*)d_in[3];
    const float* Wv = (const float*)d_in[4];
    const float* Wo = (const float*)d_in[5];
    const float* bo = (const float*)d_in[6];
    float* out = (float*)d_out;

    float *Qp, *Xf, *Af, *Wqf, *Wvf, *Wof, *Wkf;
    cudaGetSymbolAddress((void**)&Qp,  g_Q);
    cudaGetSymbolAddress((void**)&Xf,  g_Xf);
    cudaGetSymbolAddress((void**)&Af,  g_Af);
    cudaGetSymbolAddress((void**)&Wqf, g_Wqf);
    cudaGetSymbolAddress((void**)&Wvf, g_Wvf);
    cudaGetSymbolAddress((void**)&Wof, g_Wof);
    cudaGetSymbolAddress((void**)&Wkf, g_Wkf);

    const int smem_g = (8192 + 16384) * 4;        // 98304
    const int smem_f = FSM_TOT * 4;               // 223744
    cudaFuncSetAttribute(gemm_f, cudaFuncAttributeMaxDynamicSharedMemorySize, smem_g);
    cudaFuncSetAttribute(fattn, cudaFuncAttributeMaxDynamicSharedMemorySize, smem_f);

    prep_w<<<2048, 256>>>(Wq, Wk, Wv, Wo);
    prep_a<<<8192, 256>>>(x);
    // Q projection
    gemm_f<<<256, 512, smem_g>>>(Xf, Wqf, Qp, nullptr, nullptr, 0, 2);
    // fused attention with absorbed K/V projections
    fattn<<<4096, 256, smem_f>>>(Qp, l, Wkf, Wvf);
    // output projection + bias
    gemm_f<<<256, 512, smem_g>>>(Af, Wof, out, nullptr, bo, 0, 2);
}

// round 6
// speedup vs baseline: 3.1839x; 1.1755x over previous
#include <cuda_runtime.h>
#include <cstdint>
#include <cstddef>

// ---------------------------------------------------------------------------
// CrossAttentionDecoder: B=1024 (8*128), n_tok=16, num_latents=128, d=512,
// heads=8, dh=64.  Mask: batch b attends only to latents j <= (b % 128).
//
// Projection-absorbed, head-stacked formulation (K,V never materialized):
//   R = h*16 + i (0..127) stacks all heads of a batch.
//   qk[R,d] = sum_e q[b,i,h*64+e] Wk[h*64+e,d]     (per-head GEMM, phase A)
//   S[R,j]  = sum_d qk[R,d] l[b,j,d]               (M=128,N=nj,K=512)
//   P = softmax_j(S/8), masked j<=b%128
//   pl[R,d] = sum_j P[R,j] l[b,j,d]                (M=128,N=512,K=nj)
//   out[R,e]= sum_d pl[R,d] Wv[h*64+e,d]           (per-head GEMM, phase E)
// One CTA per b, 512 threads, all operands fragment-packed in smem.
// ---------------------------------------------------------------------------

#define DIMK 512

__device__ float g_Q[1024 * 16 * 512];              // 32 MB row-major q
__device__ float g_Xf[128ull * 64 * 8 * 32 * 4];    // packed x
__device__ float g_Af[128ull * 64 * 8 * 32 * 4];    // packed attn output
__device__ float g_Wqf[64 * 64 * 32 * 2];
__device__ float g_Wvf[64 * 64 * 32 * 2];
__device__ float g_Wof[64 * 64 * 32 * 2];
__device__ float g_Wkf[8 * 64 * 8 * 32 * 2];        // transposed pack for qk

// ---------------- helpers ---------------------------------------------------
__device__ __forceinline__ float to_tf32(float x) {
    uint32_t u; asm("cvt.rna.tf32.f32 %0, %1;" : "=r"(u) : "f"(x));
    return __uint_as_float(u);
}
__device__ __forceinline__ uint32_t f2u(float x) { return __float_as_uint(x); }

__device__ __forceinline__ void mma_tf32(float* d, const uint32_t* a, const uint32_t* b) {
    asm volatile(
        "mma.sync.aligned.m16n8k8.row.col.f32.tf32.tf32.f32 "
        "{%0,%1,%2,%3}, {%4,%5,%6,%7}, {%8,%9}, {%0,%1,%2,%3};\n"
        : "+f"(d[0]), "+f"(d[1]), "+f"(d[2]), "+f"(d[3])
        : "r"(a[0]), "r"(a[1]), "r"(a[2]), "r"(a[3]),
          "r"(b[0]), "r"(b[1]));
}

__device__ __forceinline__ void cp_async16(uint32_t sdst, const void* gsrc) {
    asm volatile("cp.async.ca.shared.global [%0], [%1], 16;\n" :: "r"(sdst), "l"(gsrc));
}

__device__ __forceinline__ uint32_t smem_u32(const void* p) {
    uint32_t a;
    asm("{ .reg .u64 t; cvta.to.shared.u64 t, %1; cvt.u32.u64 %0, t; }" : "=r"(a) : "l"(p));
    return a;
}

// packed-A index for value at global row R, col c  (m16n8k8 A-fragment order)
__device__ __forceinline__ size_t pidx(int R, int c) {
    int mA = R >> 7, loc = R & 127, mt = loc >> 4, rr = loc & 15;
    int gp = rr & 7, abot = rr >> 3;
    int kk = c >> 3, kb = c & 7, tgp = kb & 3, ahi = kb >> 2;
    return ((((size_t)mA * 64 + kk) * 8 + mt) * 32 + (gp * 4 + tgp)) * 4 + (abot + 2 * ahi);
}

// ---------------------------------------------------------------------------
// prep_w: fragment-pack Wq, Wv, Wo (B[n][k] = W[n][k]) and Wk transposed
// (B[n][k] = Wk[h*64+k][n]) for the in-attention qk GEMM.
// ---------------------------------------------------------------------------
__global__ __launch_bounds__(256)
void prep_w(const float* __restrict__ Wq, const float* __restrict__ Wk,
            const float* __restrict__ Wv, const float* __restrict__ Wo)
{
    int gid = blockIdx.x * 256 + threadIdx.x;        // 2048 blocks -> 524288
    int lane = gid & 31, kk = (gid >> 5) & 63, nv = gid >> 11;   // nv 0..255
    int g = lane >> 2, tg = lane & 3;
    if (nv < 192) {
        const float* W; float* dst; int dn;
        if (nv < 64)       { W = Wq; dst = g_Wqf; dn = nv; }
        else if (nv < 128) { W = Wv; dst = g_Wvf; dn = nv - 64; }
        else               { W = Wo; dst = g_Wof; dn = nv - 128; }
        float v0 = to_tf32(W[(size_t)(dn * 8 + g) * DIMK + kk * 8 + tg]);
        float v1 = to_tf32(W[(size_t)(dn * 8 + g) * DIMK + kk * 8 + tg + 4]);
        *(float2*)(dst + ((size_t)(dn * 64 + kk) * 32 + lane) * 2) = make_float2(v0, v1);
    } else {
        int t = nv - 192;            // 0..63
        int h = t >> 3, ks = t & 7;
        int ntg = kk;                // qk col-tile 0..63
        float v0 = to_tf32(Wk[(size_t)(h * 64 + ks * 8 + tg) * DIMK + ntg * 8 + g]);
        float v1 = to_tf32(Wk[(size_t)(h * 64 + ks * 8 + tg + 4) * DIMK + ntg * 8 + g]);
        *(float2*)(g_Wkf + ((size_t)((h * 64 + ntg) * 8 + ks) * 32 + lane) * 2) =
            make_float2(v0, v1);
    }
}

// ---------------------------------------------------------------------------
// prep_a: tf32-round + fragment-pack x.
// ---------------------------------------------------------------------------
__global__ __launch_bounds__(256)
void prep_a(const float* __restrict__ x)
{
    size_t gid = (size_t)blockIdx.x * 256 + threadIdx.x;   // 8192 blocks
    int lane = (int)(gid & 31), mt = (int)((gid >> 5) & 7), kk = (int)((gid >> 8) & 63);
    int mA = (int)(gid >> 14);      // 0..127
    int gp = lane >> 2, tgp = lane & 3;
    size_t R0 = (size_t)mA * 128 + mt * 16 + gp, R1 = R0 + 8;
    int c0 = kk * 8 + tgp;
    float4 v;
    v.x = to_tf32(x[R0 * DIMK + c0]);
    v.y = to_tf32(x[R1 * DIMK + c0]);
    v.z = to_tf32(x[R0 * DIMK + c0 + 4]);
    v.w = to_tf32(x[R1 * DIMK + c0 + 4]);
    *(float4*)(g_Xf + ((((size_t)mA * 64 + kk) * 8 + mt) * 32 + lane) * 4) = v;
}

// ---------------------------------------------------------------------------
// gemm_f (unchanged, verified): C = A_packed @ W_packed^T (+bias), BM=128 BN=256.
// ---------------------------------------------------------------------------
__global__ __launch_bounds__(512, 1)
void gemm_f(const float* __restrict__ Ap, const float* __restrict__ Wf,
            float* __restrict__ C0, float* __restrict__ C1,
            const float* __restrict__ bias, int masked, int nbc)
{
    extern __shared__ __align__(16) float sm[];
    float* As = sm;            // [2][4096]
    float* Ws = sm + 8192;     // [2][8192]
    const uint32_t sbA = smem_u32(sm);
    const uint32_t sbW = sbA + 8192 * 4;

    const int bx = blockIdx.x;
    const int m = bx / nbc, nb = bx - m * nbc;
    const int colbase = nb * 256;
    const int valid = masked ? (m & 127) + 1 : 128;
    const int tid = threadIdx.x;
    const int warp = tid >> 5, lane = tid & 31;
    const int wm = warp >> 2, wn = warp & 3;
    const int g = lane >> 2, tg = lane & 3;
    const bool active = (wm * 32) < valid;

    const float* Abase = Ap + (size_t)m * 65536;
    const float* Wbase = Wf + (size_t)(colbase >> 3) * 4096;

    float acc[2][8][4];
    #pragma unroll
    for (int i = 0; i < 2; i++)
        #pragma unroll
        for (int j = 0; j < 8; j++)
            #pragma unroll
            for (int c = 0; c < 4; c++) acc[i][j][c] = 0.f;

    auto do_stage = [&](int it) {
        const int s = it & 1;
        uint32_t Ad = sbA + s * 16384;
        uint32_t Wd = sbW + s * 32768;
        const float* Asrc = Abase + (size_t)it * 4096;
        cp_async16(Ad + tid * 16, Asrc + tid * 4);
        cp_async16(Ad + (tid + 512) * 16, Asrc + (tid + 512) * 4);
        #pragma unroll
        for (int i = 0; i < 4; i++) {
            int j = tid + i * 512;
            int nt8l = j >> 6, w2 = j & 63;
            cp_async16(Wd + (uint32_t)(nt8l * 1024 + w2 * 16),
                       Wbase + (size_t)nt8l * 4096 + it * 256 + w2 * 4);
        }
        asm volatile("cp.async.commit_group;\n" ::: "memory");
    };

    do_stage(0);
    do_stage(1);

    for (int it = 0; it < 16; ++it) {
        if (it < 15) asm volatile("cp.async.wait_group 1;\n" ::: "memory");
        else         asm volatile("cp.async.wait_group 0;\n" ::: "memory");
        __syncthreads();
        if (active) {
            const float* Ac = As + (it & 1) * 4096;
            const float* Wc = Ws + (it & 1) * 8192;
            #pragma unroll
            for (int kk = 0; kk < 4; ++kk) {
                const float* Ab = Ac + kk * 1024;
                uint4 a0 = *(const uint4*)(Ab + (wm * 2 + 0) * 128 + lane * 4);
                uint4 a1 = *(const uint4*)(Ab + (wm * 2 + 1) * 128 + lane * 4);
                uint32_t au0[4] = {a0.x, a0.y, a0.z, a0.w};
                uint32_t au1[4] = {a1.x, a1.y, a1.z, a1.w};
                #pragma unroll
                for (int nt = 0; nt < 8; ++nt) {
                    int nt8l = wn * 8 + nt;
                    float2 bv = *(const float2*)(Wc + nt8l * 256 + kk * 64 + lane * 2);
                    uint32_t bu[2] = {f2u(bv.x), f2u(bv.y)};
                    mma_tf32(acc[0][nt], au0, bu);
                    mma_tf32(acc[1][nt], au1, bu);
                }
            }
        }
        __syncthreads();
        if (it + 2 < 16) do_stage(it + 2);
    }

    if (!active) return;
    #pragma unroll
    for (int mt = 0; mt < 2; ++mt) {
        int r0 = wm * 32 + mt * 16 + g;
        int r1 = r0 + 8;
        #pragma unroll
        for (int nt = 0; nt < 8; ++nt) {
            int c = colbase + wn * 64 + nt * 8 + 2 * tg;
            int cr = c & 511;
            float* C = (c < 512) ? C0 : C1;
            float b0 = 0.f, b1 = 0.f;
            if (bias) { b0 = bias[cr]; b1 = bias[cr + 1]; }
            if (r0 < valid)
                *(float2*)(C + ((size_t)m * 128 + r0) * DIMK + cr) =
                    make_float2(acc[mt][nt][0] + b0, acc[mt][nt][1] + b1);
            if (r1 < valid)
                *(float2*)(C + ((size_t)m * 128 + r1) * DIMK + cr) =
                    make_float2(acc[mt][nt][2] + b0, acc[mt][nt][3] + b1);
        }
    }
}

// ---------------------------------------------------------------------------
// fattn2: one CTA per batch b, 512 threads (16 warps).
// Smem (floats): qf[8][8][32][4] | qkc/plc[8][8][32][4] | lc 8192 | Ps 128x132
// ---------------------------------------------------------------------------
#define FSM2_Q   0
#define FSM2_QKC 8192
#define FSM2_LC  16384
#define FSM2_PS  24576
#define FSM2_TOT 41472     // floats -> 165888 bytes

__global__ __launch_bounds__(512, 1)
void fattn2(const float* __restrict__ Q, const float* __restrict__ l,
            const float* __restrict__ Wkf, const float* __restrict__ Wvf)
{
    extern __shared__ __align__(16) float sm[];
    float* qf  = sm + FSM2_Q;
    float* qkc = sm + FSM2_QKC;      // reused as plc in pass 2
    float* lc  = sm + FSM2_LC;
    float* Ps  = sm + FSM2_PS;

    const int b = blockIdx.x;
    const int nj = (b & 127) + 1;
    const int njc32 = (nj + 31) & ~31;
    const int tid = threadIdx.x, w = tid >> 5, lane = tid & 31;
    const int g = lane >> 2, tg = lane & 3;
    const int wm = w >> 2, wn = w & 3;       // scores mapping (4m x 4n)
    const int amt = w >> 1, anh = w & 1;     // phase A / pass2 / ov mapping

    // ---- stage q -> qf (a-frag packed, m-tile = head) ----
    for (int idx = tid; idx < 2048; idx += 512) {
        int i = idx >> 7, col = (idx & 127) * 4;
        int h = col >> 6;
        float4 v = *(const float4*)(Q + ((size_t)(b * 16 + i)) * 512 + col);
        float vv[4] = {v.x, v.y, v.z, v.w};
        #pragma unroll
        for (int c = 0; c < 4; c++) {
            int e = (col & 63) + c;
            int ks = e >> 3, ln = (i & 7) * 4 + (e & 3);
            int slot = (i >> 3) + 2 * ((e >> 2) & 1);
            qf[((h * 8 + ks) * 32 + ln) * 4 + slot] = to_tf32(vv[c]);
        }
    }

    float sacc[2][4][4];
    #pragma unroll
    for (int i = 0; i < 2; i++)
        #pragma unroll
        for (int j = 0; j < 4; j++)
            #pragma unroll
            for (int c = 0; c < 4; c++) sacc[i][j][c] = 0.f;

    // ================= pass 1: scores =================
    for (int ch = 0; ch < 8; ch++) {
        const int d0 = ch * 64;
        __syncthreads();   // prev scores done with lc/qkc; ch=0: qf staged

        // stage lc, pass-1 b-frag layout [jt16][ksd8][lane][2]
        for (int idx = tid; idx < njc32 * 16; idx += 512) {
            int j = idx >> 4, dq = idx & 15;
            float4 v = make_float4(0.f, 0.f, 0.f, 0.f);
            if (j < nj)
                v = *(const float4*)(l + ((size_t)(b * 128 + j)) * 512 + d0 + dq * 4);
            float vv[4] = {v.x, v.y, v.z, v.w};
            int base = ((j >> 3) * 8 + (dq >> 1)) * 32 + (j & 7) * 4;
            int slot = dq & 1;
            #pragma unroll
            for (int c = 0; c < 4; c++)
                lc[(base + c) * 2 + slot] = to_tf32(vv[c]);
        }

        // phase A: qk-chunk = q_h @ Wk_h[:, d0:d0+64]  (regs only)
        float aacc[4][4];
        #pragma unroll
        for (int nt = 0; nt < 4; nt++)
            #pragma unroll
            for (int c = 0; c < 4; c++) aacc[nt][c] = 0.f;
        {
            const float* wkb = Wkf + (size_t)(amt * 64 + ch * 8 + anh * 4) * 512 + lane * 2;
            uint2 bp[4];
            #pragma unroll
            for (int nt = 0; nt < 4; nt++) bp[nt] = *(const uint2*)(wkb + nt * 512);
            #pragma unroll
            for (int ks = 0; ks < 8; ks++) {
                float4 af = *(const float4*)(qf + ((amt * 8 + ks) * 32 + lane) * 4);
                uint32_t a[4] = {f2u(af.x), f2u(af.y), f2u(af.z), f2u(af.w)};
                uint2 bc[4];
                #pragma unroll
                for (int nt = 0; nt < 4; nt++) bc[nt] = bp[nt];
                if (ks < 7) {
                    #pragma unroll
                    for (int nt = 0; nt < 4; nt++)
                        bp[nt] = *(const uint2*)(wkb + nt * 512 + (ks + 1) * 64);
                }
                #pragma unroll
                for (int nt = 0; nt < 4; nt++)
                    mma_tf32(aacc[nt], a, (const uint32_t*)&bc[nt]);
            }
        }
        // scatter qk-chunk into a-frag-packed qkc
        #pragma unroll
        for (int nt = 0; nt < 4; nt++) {
            int c0 = anh * 32 + nt * 8 + 2 * tg;
            #pragma unroll
            for (int e = 0; e < 4; e++) {
                int r = g + ((e >> 1) << 3);
                int c = c0 + (e & 1);
                int ksd = c >> 3, ln = (r & 7) * 4 + (c & 3);
                int slot = (r >> 3) + 2 * ((c >> 2) & 1);
                qkc[((amt * 8 + ksd) * 32 + ln) * 4 + slot] = to_tf32(aacc[nt][e]);
            }
        }
        __syncthreads();

        // scores mma: S += qkc @ lc^T
        if (wn * 32 < njc32) {
            #pragma unroll
            for (int ksd = 0; ksd < 8; ksd++) {
                float4 af0 = *(const float4*)(qkc + (((wm * 2 + 0) * 8 + ksd) * 32 + lane) * 4);
                float4 af1 = *(const float4*)(qkc + (((wm * 2 + 1) * 8 + ksd) * 32 + lane) * 4);
                uint32_t a0[4] = {f2u(af0.x), f2u(af0.y), f2u(af0.z), f2u(af0.w)};
                uint32_t a1[4] = {f2u(af1.x), f2u(af1.y), f2u(af1.z), f2u(af1.w)};
                #pragma unroll
                for (int jt4 = 0; jt4 < 4; jt4++) {
                    int jt = wn * 4 + jt4;
                    uint2 bf = *(const uint2*)(lc + ((jt * 8 + ksd) * 32 + lane) * 2);
                    mma_tf32(sacc[0][jt4], a0, (const uint32_t*)&bf);
                    mma_tf32(sacc[1][jt4], a1, (const uint32_t*)&bf);
                }
            }
        }
    }
    __syncthreads();

    // ---- write scores -> Ps (scaled) ----
    if (wn * 32 < njc32) {
        #pragma unroll
        for (int mt = 0; mt < 2; mt++) {
            int r0 = wm * 32 + mt * 16;
            #pragma unroll
            for (int jt4 = 0; jt4 < 4; jt4++) {
                int jc = wn * 32 + jt4 * 8 + 2 * tg;
                Ps[(r0 + g) * 132 + jc]         = sacc[mt][jt4][0] * 0.125f;
                Ps[(r0 + g) * 132 + jc + 1]     = sacc[mt][jt4][1] * 0.125f;
                Ps[(r0 + g + 8) * 132 + jc]     = sacc[mt][jt4][2] * 0.125f;
                Ps[(r0 + g + 8) * 132 + jc + 1] = sacc[mt][jt4][3] * 0.125f;
            }
        }
    }
    __syncthreads();

    // ---- softmax: warp w owns rows w*8 .. w*8+7 ----
    #pragma unroll
    for (int rr = 0; rr < 8; rr++) {
        int row = w * 8 + rr;
        float* p = Ps + row * 132;
        float mx = -1e30f;
        for (int j = lane; j < nj; j += 32) mx = fmaxf(mx, p[j]);
        #pragma unroll
        for (int o = 16; o; o >>= 1) mx = fmaxf(mx, __shfl_xor_sync(0xffffffffu, mx, o));
        float e4[4]; int cnt = 0; float s = 0.f;
        for (int j = lane; j < nj; j += 32) { float ev = __expf(p[j] - mx); e4[cnt++] = ev; s += ev; }
        #pragma unroll
        for (int o = 16; o; o >>= 1) s += __shfl_xor_sync(0xffffffffu, s, o);
        float inv = 1.f / s;
        cnt = 0;
        for (int j = lane; j < njc32; j += 32) {
            float val = (j < nj) ? e4[cnt++] * inv : 0.f;
            p[j] = to_tf32(val);
        }
    }

    // ================= pass 2: pl + ov =================
    float ovacc[4][4];
    #pragma unroll
    for (int nt = 0; nt < 4; nt++)
        #pragma unroll
        for (int c = 0; c < 4; c++) ovacc[nt][c] = 0.f;
    const int ksjmax = njc32 >> 3;

    for (int ch = 0; ch < 8; ch++) {
        const int d0 = ch * 64;
        __syncthreads();   // prev ov done with plc; prev pass2 done with lc; softmax done

        // stage lc, pass-2 b-frag layout [nt8][ksj16][lane][2]
        for (int idx = tid; idx < njc32 * 16; idx += 512) {
            int j = idx >> 4, dq = idx & 15;
            float4 v = make_float4(0.f, 0.f, 0.f, 0.f);
            if (j < nj)
                v = *(const float4*)(l + ((size_t)(b * 128 + j)) * 512 + d0 + dq * 4);
            float vv[4] = {v.x, v.y, v.z, v.w};
            int slot = (j >> 2) & 1;
            #pragma unroll
            for (int c = 0; c < 4; c++) {
                int dl = dq * 4 + c;
                int ln = (dl & 7) * 4 + (j & 3);
                lc[(((dl >> 3) * 16 + (j >> 3)) * 32 + ln) * 2 + slot] = to_tf32(vv[c]);
            }
        }
        __syncthreads();

        // pl-chunk = P @ lc
        float placc[4][4];
        #pragma unroll
        for (int nt = 0; nt < 4; nt++)
            #pragma unroll
            for (int c = 0; c < 4; c++) placc[nt][c] = 0.f;
        for (int ksj = 0; ksj < ksjmax; ksj++) {
            const float* pr = Ps + (amt * 16) * 132 + ksj * 8;
            uint32_t a[4] = { f2u(pr[g * 132 + tg]),       f2u(pr[(g + 8) * 132 + tg]),
                              f2u(pr[g * 132 + tg + 4]),   f2u(pr[(g + 8) * 132 + tg + 4]) };
            #pragma unroll
            for (int nt = 0; nt < 4; nt++) {
                uint2 bf = *(const uint2*)(lc + (((anh * 4 + nt) * 16 + ksj) * 32 + lane) * 2);
                mma_tf32(placc[nt], a, (const uint32_t*)&bf);
            }
        }
        // scatter pl-chunk into a-frag-packed plc (qkc buffer)
        #pragma unroll
        for (int nt = 0; nt < 4; nt++) {
            int c0 = anh * 32 + nt * 8 + 2 * tg;
            #pragma unroll
            for (int e = 0; e < 4; e++) {
                int r = g + ((e >> 1) << 3);
                int c = c0 + (e & 1);
                int ksd = c >> 3, ln = (r & 7) * 4 + (c & 3);
                int slot = (r >> 3) + 2 * ((c >> 2) & 1);
                qkc[((amt * 8 + ksd) * 32 + ln) * 4 + slot] = to_tf32(placc[nt][e]);
            }
        }
        __syncthreads();

        // ov += pl-chunk @ Wv_h-chunk^T  (b from L2-hot g_Wvf, 1-deep prefetch)
        {
            const float* wvb = Wvf + (size_t)(amt * 8 + anh * 4) * 4096 + ch * 512 + lane * 2;
            uint2 bp[4];
            #pragma unroll
            for (int nt = 0; nt < 4; nt++) bp[nt] = *(const uint2*)(wvb + nt * 4096);
            #pragma unroll
            for (int ksd = 0; ksd < 8; ksd++) {
                float4 af = *(const float4*)(qkc + ((amt * 8 + ksd) * 32 + lane) * 4);
                uint32_t a[4] = {f2u(af.x), f2u(af.y), f2u(af.z), f2u(af.w)};
                uint2 bc[4];
                #pragma unroll
                for (int nt = 0; nt < 4; nt++) bc[nt] = bp[nt];
                if (ksd < 7) {
                    #pragma unroll
                    for (int nt = 0; nt < 4; nt++)
                        bp[nt] = *(const uint2*)(wvb + nt * 4096 + (ksd + 1) * 64);
                }
                #pragma unroll
                for (int nt = 0; nt < 4; nt++)
                    mma_tf32(ovacc[nt], a, (const uint32_t*)&bc[nt]);
            }
        }
    }

    // ---- final store: out[R=(amt,i), e] -> packed g_Af ----
    #pragma unroll
    for (int nt = 0; nt < 4; nt++) {
        int col = amt * 64 + anh * 32 + nt * 8 + 2 * tg;
        int R0 = b * 16 + g;
        g_Af[pidx(R0, col)]         = to_tf32(ovacc[nt][0]);
        g_Af[pidx(R0, col + 1)]     = to_tf32(ovacc[nt][1]);
        g_Af[pidx(R0 + 8, col)]     = to_tf32(ovacc[nt][2]);
        g_Af[pidx(R0 + 8, col + 1)] = to_tf32(ovacc[nt][3]);
    }
}

// ---------------------------------------------------------------------------
extern "C" void kernel_launch(void* const* d_in, const int* in_sizes, int n_in,
                              void* d_out, int out_size)
{
    const float* x  = (const float*)d_in[0];
    const float* l  = (const float*)d_in[1];
    const float* Wq = (const float*)d_in[2];
    const float* Wk = (const float*)d_in[3];
    const float* Wv = (const float*)d_in[4];
    const float* Wo = (const float*)d_in[5];
    const float* bo = (const float*)d_in[6];
    float* out = (float*)d_out;

    float *Qp, *Xf, *Af, *Wqf, *Wvf, *Wof, *Wkf;
    cudaGetSymbolAddress((void**)&Qp,  g_Q);
    cudaGetSymbolAddress((void**)&Xf,  g_Xf);
    cudaGetSymbolAddress((void**)&Af,  g_Af);
    cudaGetSymbolAddress((void**)&Wqf, g_Wqf);
    cudaGetSymbolAddress((void**)&Wvf, g_Wvf);
    cudaGetSymbolAddress((void**)&Wof, g_Wof);
    cudaGetSymbolAddress((void**)&Wkf, g_Wkf);

    const int smem_g = (8192 + 16384) * 4;   // 98304
    const int smem_f = FSM2_TOT * 4;         // 165888
    cudaFuncSetAttribute(gemm_f, cudaFuncAttributeMaxDynamicSharedMemorySize, smem_g);
    cudaFuncSetAttribute(fattn2, cudaFuncAttributeMaxDynamicSharedMemorySize, smem_f);

    prep_w<<<2048, 256>>>(Wq, Wk, Wv, Wo);
    prep_a<<<8192, 256>>>(x);
    // Q projection
    gemm_f<<<256, 512, smem_g>>>(Xf, Wqf, Qp, nullptr, nullptr, 0, 2);
    // fused head-stacked attention with absorbed K/V projections
    fattn2<<<1024, 512, smem_f>>>(Qp, l, Wkf, Wvf);
    // output projection + bias
    gemm_f<<<256, 512, smem_g>>>(Af, Wof, out, nullptr, bo, 0, 2);
}

// round 8
// speedup vs baseline: 3.7524x; 1.1786x over previous
#include <cuda_runtime.h>
#include <cstdint>
#include <cstddef>

// ---------------------------------------------------------------------------
// CrossAttentionDecoder: B=1024 (8*128), n_tok=16, num_latents=128, d=512,
// heads=8, dh=64.  Mask: batch b attends only to latents j <= (b % 128).
//
// Projection-absorbed, head-stacked formulation (K,V never materialized):
//   R = h*16 + i stacks heads.  qk = q@Wk_h, S = qk@l^T, P = softmax(S/8),
//   pl = P@l, out = pl@Wv_h^T.  One CTA per b, 512 threads.
// l staged per 64-d chunk into a unified 8x8-tile smem layout (XOR cell
// permutation, stride 68) serving both passes with conflict-free STS.128
// staging and conflict-free LDS.32 fragment reads.
// ---------------------------------------------------------------------------

#define DIMK 512

__device__ float g_Qf[1024ull * 8 * 8 * 128];       // packed q a-frags (4 MB)
__device__ float g_Xf[128ull * 64 * 8 * 32 * 4];    // packed x
__device__ float g_Af[128ull * 64 * 8 * 32 * 4];    // packed attn output
__device__ float g_Wqf[64 * 64 * 32 * 2];
__device__ float g_Wvf[64 * 64 * 32 * 2];
__device__ float g_Wof[64 * 64 * 32 * 2];
__device__ float g_Wkf[8 * 64 * 8 * 32 * 2];        // transposed pack for qk

// ---------------- helpers ---------------------------------------------------
__device__ __forceinline__ float to_tf32(float x) {
    uint32_t u; asm("cvt.rna.tf32.f32 %0, %1;" : "=r"(u) : "f"(x));
    return __uint_as_float(u);
}
__device__ __forceinline__ uint32_t f2u(float x) { return __float_as_uint(x); }

__device__ __forceinline__ void mma_tf32(float* d, const uint32_t* a, const uint32_t* b) {
    asm volatile(
        "mma.sync.aligned.m16n8k8.row.col.f32.tf32.tf32.f32 "
        "{%0,%1,%2,%3}, {%4,%5,%6,%7}, {%8,%9}, {%0,%1,%2,%3};\n"
        : "+f"(d[0]), "+f"(d[1]), "+f"(d[2]), "+f"(d[3])
        : "r"(a[0]), "r"(a[1]), "r"(a[2]), "r"(a[3]),
          "r"(b[0]), "r"(b[1]));
}

__device__ __forceinline__ void cp_async16(uint32_t sdst, const void* gsrc) {
    asm volatile("cp.async.ca.shared.global [%0], [%1], 16;\n" :: "r"(sdst), "l"(gsrc));
}

__device__ __forceinline__ uint32_t smem_u32(const void* p) {
    uint32_t a;
    asm("{ .reg .u64 t; cvta.to.shared.u64 t, %1; cvt.u32.u64 %0, t; }" : "=r"(a) : "l"(p));
    return a;
}

// packed-A index for value at global row R, col c  (m16n8k8 A-fragment order)
__device__ __forceinline__ size_t pidx(int R, int c) {
    int mA = R >> 7, loc = R & 127, mt = loc >> 4, rr = loc & 15;
    int gp = rr & 7, abot = rr >> 3;
    int kk = c >> 3, kb = c & 7, tgp = kb & 3, ahi = kb >> 2;
    return ((((size_t)mA * 64 + kk) * 8 + mt) * 32 + (gp * 4 + tgp)) * 4 + (abot + 2 * ahi);
}

// ---------------------------------------------------------------------------
__global__ __launch_bounds__(256)
void prep_w(const float* __restrict__ Wq, const float* __restrict__ Wk,
            const float* __restrict__ Wv, const float* __restrict__ Wo)
{
    int gid = blockIdx.x * 256 + threadIdx.x;        // 2048 blocks
    int lane = gid & 31, kk = (gid >> 5) & 63, nv = gid >> 11;   // nv 0..255
    int g = lane >> 2, tg = lane & 3;
    if (nv < 192) {
        const float* W; float* dst; int dn;
        if (nv < 64)       { W = Wq; dst = g_Wqf; dn = nv; }
        else if (nv < 128) { W = Wv; dst = g_Wvf; dn = nv - 64; }
        else               { W = Wo; dst = g_Wof; dn = nv - 128; }
        float v0 = to_tf32(W[(size_t)(dn * 8 + g) * DIMK + kk * 8 + tg]);
        float v1 = to_tf32(W[(size_t)(dn * 8 + g) * DIMK + kk * 8 + tg + 4]);
        *(float2*)(dst + ((size_t)(dn * 64 + kk) * 32 + lane) * 2) = make_float2(v0, v1);
    } else {
        int t = nv - 192;            // 0..63
        int h = t >> 3, ks = t & 7;
        int ntg = kk;
        float v0 = to_tf32(Wk[(size_t)(h * 64 + ks * 8 + tg) * DIMK + ntg * 8 + g]);
        float v1 = to_tf32(Wk[(size_t)(h * 64 + ks * 8 + tg + 4) * DIMK + ntg * 8 + g]);
        *(float2*)(g_Wkf + ((size_t)((h * 64 + ntg) * 8 + ks) * 32 + lane) * 2) =
            make_float2(v0, v1);
    }
}

// ---------------------------------------------------------------------------
__global__ __launch_bounds__(256)
void prep_a(const float* __restrict__ x)
{
    size_t gid = (size_t)blockIdx.x * 256 + threadIdx.x;   // 8192 blocks
    int lane = (int)(gid & 31), mt = (int)((gid >> 5) & 7), kk = (int)((gid >> 8) & 63);
    int mA = (int)(gid >> 14);
    int gp = lane >> 2, tgp = lane & 3;
    size_t R0 = (size_t)mA * 128 + mt * 16 + gp, R1 = R0 + 8;
    int c0 = kk * 8 + tgp;
    float4 v;
    v.x = to_tf32(x[R0 * DIMK + c0]);
    v.y = to_tf32(x[R1 * DIMK + c0]);
    v.z = to_tf32(x[R0 * DIMK + c0 + 4]);
    v.w = to_tf32(x[R1 * DIMK + c0 + 4]);
    *(float4*)(g_Xf + ((((size_t)mA * 64 + kk) * 8 + mt) * 32 + lane) * 4) = v;
}

// ---------------------------------------------------------------------------
// gemm_f: C = A_packed @ W_packed^T (+bias).  packq: write q a-frag packed.
// ---------------------------------------------------------------------------
__global__ __launch_bounds__(512, 1)
void gemm_f(const float* __restrict__ Ap, const float* __restrict__ Wf,
            float* __restrict__ C0, float* __restrict__ C1,
            const float* __restrict__ bias, int masked, int nbc, int packq)
{
    extern __shared__ __align__(16) float sm[];
    float* As = sm;            // [2][4096]
    float* Ws = sm + 8192;     // [2][8192]
    const uint32_t sbA = smem_u32(sm);
    const uint32_t sbW = sbA + 8192 * 4;

    const int bx = blockIdx.x;
    const int m = bx / nbc, nb = bx - m * nbc;
    const int colbase = nb * 256;
    const int valid = masked ? (m & 127) + 1 : 128;
    const int tid = threadIdx.x;
    const int warp = tid >> 5, lane = tid & 31;
    const int wm = warp >> 2, wn = warp & 3;
    const int g = lane >> 2, tg = lane & 3;
    const bool active = (wm * 32) < valid;

    const float* Abase = Ap + (size_t)m * 65536;
    const float* Wbase = Wf + (size_t)(colbase >> 3) * 4096;

    float acc[2][8][4];
    #pragma unroll
    for (int i = 0; i < 2; i++)
        #pragma unroll
        for (int j = 0; j < 8; j++)
            #pragma unroll
            for (int c = 0; c < 4; c++) acc[i][j][c] = 0.f;

    auto do_stage = [&](int it) {
        const int s = it & 1;
        uint32_t Ad = sbA + s * 16384;
        uint32_t Wd = sbW + s * 32768;
        const float* Asrc = Abase + (size_t)it * 4096;
        cp_async16(Ad + tid * 16, Asrc + tid * 4);
        cp_async16(Ad + (tid + 512) * 16, Asrc + (tid + 512) * 4);
        #pragma unroll
        for (int i = 0; i < 4; i++) {
            int j = tid + i * 512;
            int nt8l = j >> 6, w2 = j & 63;
            cp_async16(Wd + (uint32_t)(nt8l * 1024 + w2 * 16),
                       Wbase + (size_t)nt8l * 4096 + it * 256 + w2 * 4);
        }
        asm volatile("cp.async.commit_group;\n" ::: "memory");
    };

    do_stage(0);
    do_stage(1);

    for (int it = 0; it < 16; ++it) {
        if (it < 15) asm volatile("cp.async.wait_group 1;\n" ::: "memory");
        else         asm volatile("cp.async.wait_group 0;\n" ::: "memory");
        __syncthreads();
        if (active) {
            const float* Ac = As + (it & 1) * 4096;
            const float* Wc = Ws + (it & 1) * 8192;
            #pragma unroll
            for (int kk = 0; kk < 4; ++kk) {
                const float* Ab = Ac + kk * 1024;
                uint4 a0 = *(const uint4*)(Ab + (wm * 2 + 0) * 128 + lane * 4);
                uint4 a1 = *(const uint4*)(Ab + (wm * 2 + 1) * 128 + lane * 4);
                uint32_t au0[4] = {a0.x, a0.y, a0.z, a0.w};
                uint32_t au1[4] = {a1.x, a1.y, a1.z, a1.w};
                #pragma unroll
                for (int nt = 0; nt < 8; ++nt) {
                    int nt8l = wn * 8 + nt;
                    float2 bv = *(const float2*)(Wc + nt8l * 256 + kk * 64 + lane * 2);
                    uint32_t bu[2] = {f2u(bv.x), f2u(bv.y)};
                    mma_tf32(acc[0][nt], au0, bu);
                    mma_tf32(acc[1][nt], au1, bu);
                }
            }
        }
        __syncthreads();
        if (it + 2 < 16) do_stage(it + 2);
    }

    if (!active) return;
    if (packq) {
        #pragma unroll
        for (int mt = 0; mt < 2; ++mt) {
            #pragma unroll
            for (int nt = 0; nt < 8; ++nt) {
                int c = colbase + wn * 64 + nt * 8 + 2 * tg;
                #pragma unroll
                for (int e = 0; e < 4; e++) {
                    int r = wm * 32 + mt * 16 + g + ((e >> 1) << 3);
                    int cc = c + (e & 1);
                    int R = m * 128 + r;
                    int bq = R >> 4, i = R & 15;
                    int h = cc >> 6, ksq = (cc & 63) >> 3;
                    int ln = (i & 7) * 4 + (cc & 3);
                    int slot = (i >> 3) + 2 * ((cc >> 2) & 1);
                    C0[(((size_t)bq * 8 + h) * 8 + ksq) * 128 + ln * 4 + slot] =
                        to_tf32(acc[mt][nt][e]);
                }
            }
        }
        return;
    }
    #pragma unroll
    for (int mt = 0; mt < 2; ++mt) {
        int r0 = wm * 32 + mt * 16 + g;
        int r1 = r0 + 8;
        #pragma unroll
        for (int nt = 0; nt < 8; ++nt) {
            int c = colbase + wn * 64 + nt * 8 + 2 * tg;
            int cr = c & 511;
            float* C = (c < 512) ? C0 : C1;
            float b0 = 0.f, b1 = 0.f;
            if (bias) { b0 = bias[cr]; b1 = bias[cr + 1]; }
            if (r0 < valid)
                *(float2*)(C + ((size_t)m * 128 + r0) * DIMK + cr) =
                    make_float2(acc[mt][nt][0] + b0, acc[mt][nt][1] + b1);
            if (r1 < valid)
                *(float2*)(C + ((size_t)m * 128 + r1) * DIMK + cr) =
                    make_float2(acc[mt][nt][2] + b0, acc[mt][nt][3] + b1);
        }
    }
}

// ---------------------------------------------------------------------------
// fattn3: one CTA per batch b (heavy-first order), 512 threads.
// Smem (floats): qkc 8192 | lc 8704 (128 tiles x 68) | Ps 128x132
// ---------------------------------------------------------------------------
#define F3_QKC 0
#define F3_LC  8192
#define F3_PS  16896
#define F3_TOT 33792      // floats -> 135168 bytes

__global__ __launch_bounds__(512, 1)
void fattn3(const float* __restrict__ Qf, const float* __restrict__ l,
            const float* __restrict__ Wkf, const float* __restrict__ Wvf)
{
    extern __shared__ __align__(16) float sm[];
    float* qkc = sm + F3_QKC;
    float* lc  = sm + F3_LC;
    float* Ps  = sm + F3_PS;

    const int bid = blockIdx.x;
    const int b = (bid & 7) * 128 + (127 - (bid >> 3));   // heavy-first
    const int nj = (b & 127) + 1;
    const int T = (nj + 7) >> 3;
    const int njc8 = T << 3;

    const int tid = threadIdx.x, w = tid >> 5, lane = tid & 31;
    const int g = lane >> 2, tg = lane & 3;
    const int wm = w >> 2, wn = w & 3;        // scores mapping
    const int amt = w >> 1, anh = w & 1;      // phase A / pass2 / ov mapping

    // conflict-free per-lane tile read offsets
    const int p1o0 = g * 4 + tg;                          // pass1 b0
    const int p1o1 = ((g ^ 4) + 8) * 4 + tg;              // pass1 b1
    const int h2 = g >> 2, gl = g & 3;
    const int p2o0 = ((tg ^ (h2 << 2)) + (h2 << 3)) * 4 + gl;         // pass2 b0
    const int p2o1 = (((tg + 4) ^ (h2 << 2)) + (h2 << 3)) * 4 + gl;   // pass2 b1

    // ---- unified l-chunk staging: tiles [jt*8+dtile] of 8x8, stride 68 ----
    auto stageL = [&](int ch) {
        const int lim = njc8 << 4;
        for (int idx = tid; idx < lim; idx += 512) {
            int j = idx >> 4, dq = idx & 15;
            float4 v = make_float4(0.f, 0.f, 0.f, 0.f);
            if (j < nj)
                v = *(const float4*)(l + ((size_t)(b * 128 + j)) * 512 + ch * 64 + dq * 4);
            int h = dq & 1;
            int X = ((j & 7) ^ (h << 2)) + (h << 3);
            float4 o;
            o.x = to_tf32(v.x); o.y = to_tf32(v.y); o.z = to_tf32(v.z); o.w = to_tf32(v.w);
            *(float4*)(lc + ((j >> 3) * 8 + (dq >> 1)) * 68 + X * 4) = o;
        }
    };

    float sacc[2][4][4];
    #pragma unroll
    for (int i = 0; i < 2; i++)
        #pragma unroll
        for (int j = 0; j < 4; j++)
            #pragma unroll
            for (int c = 0; c < 4; c++) sacc[i][j][c] = 0.f;

    // ================= pass 1: scores =================
    const float* qa = Qf + ((size_t)b * 8 + amt) * 1024 + lane * 4;
    for (int ch = 0; ch < 8; ch++) {
        __syncthreads();          // lc/qkc free from previous scores
        stageL(ch);

        // phase A: qk-chunk = q_h @ Wk_h[:, ch*64 : +64]
        float aacc[4][4];
        #pragma unroll
        for (int nt = 0; nt < 4; nt++)
            #pragma unroll
            for (int c = 0; c < 4; c++) aacc[nt][c] = 0.f;
        {
            const float* wkb = Wkf + ((size_t)(amt * 64 + ch * 8 + anh * 4)) * 512 + lane * 2;
            float4 ap = *(const float4*)qa;
            uint2 bp[4];
            #pragma unroll
            for (int nt = 0; nt < 4; nt++) bp[nt] = *(const uint2*)(wkb + nt * 512);
            #pragma unroll
            for (int ks = 0; ks < 8; ks++) {
                float4 ac = ap;
                uint2 bc[4];
                #pragma unroll
                for (int nt = 0; nt < 4; nt++) bc[nt] = bp[nt];
                if (ks < 7) {
                    ap = *(const float4*)(qa + (ks + 1) * 128);
                    #pragma unroll
                    for (int nt = 0; nt < 4; nt++)
                        bp[nt] = *(const uint2*)(wkb + nt * 512 + (ks + 1) * 64);
                }
                uint32_t a[4] = {f2u(ac.x), f2u(ac.y), f2u(ac.z), f2u(ac.w)};
                #pragma unroll
                for (int nt = 0; nt < 4; nt++)
                    mma_tf32(aacc[nt], a, (const uint32_t*)&bc[nt]);
            }
        }
        // scatter qk-chunk into a-frag packed qkc
        #pragma unroll
        for (int nt = 0; nt < 4; nt++) {
            int c0 = anh * 32 + nt * 8 + 2 * tg;
            #pragma unroll
            for (int e = 0; e < 4; e++) {
                int r = g + ((e >> 1) << 3);
                int c = c0 + (e & 1);
                qkc[((amt * 8 + (c >> 3)) * 32 + g * 4 + (c & 3)) * 4 +
                    ((r >> 3) + 2 * ((c >> 2) & 1))] = to_tf32(aacc[nt][e]);
            }
        }
        __syncthreads();

        // scores mma
        if (wn < T) {
            #pragma unroll
            for (int ksd = 0; ksd < 8; ksd++) {
                float4 af0 = *(const float4*)(qkc + ((wm * 2 + 0) * 8 + ksd) * 128 + lane * 4);
                float4 af1 = *(const float4*)(qkc + ((wm * 2 + 1) * 8 + ksd) * 128 + lane * 4);
                uint32_t a0[4] = {f2u(af0.x), f2u(af0.y), f2u(af0.z), f2u(af0.w)};
                uint32_t a1[4] = {f2u(af1.x), f2u(af1.y), f2u(af1.z), f2u(af1.w)};
                #pragma unroll
                for (int jt4 = 0; jt4 < 4; jt4++) {
                    int jt = wn + jt4 * 4;
                    if (jt < T) {
                        int tb = (jt * 8 + ksd) * 68;
                        uint32_t bu[2] = { f2u(lc[tb + p1o0]), f2u(lc[tb + p1o1]) };
                        mma_tf32(sacc[0][jt4], a0, bu);
                        mma_tf32(sacc[1][jt4], a1, bu);
                    }
                }
            }
        }
    }
    __syncthreads();

    // ---- write scores -> Ps (scaled) ----
    if (wn < T) {
        #pragma unroll
        for (int mt = 0; mt < 2; mt++) {
            int r0 = wm * 32 + mt * 16;
            #pragma unroll
            for (int jt4 = 0; jt4 < 4; jt4++) {
                int jt = wn + jt4 * 4;
                if (jt < T) {
                    int jc = jt * 8 + 2 * tg;
                    Ps[(r0 + g) * 132 + jc]         = sacc[mt][jt4][0] * 0.125f;
                    Ps[(r0 + g) * 132 + jc + 1]     = sacc[mt][jt4][1] * 0.125f;
                    Ps[(r0 + g + 8) * 132 + jc]     = sacc[mt][jt4][2] * 0.125f;
                    Ps[(r0 + g + 8) * 132 + jc + 1] = sacc[mt][jt4][3] * 0.125f;
                }
            }
        }
    }
    __syncthreads();

    // ---- softmax: warp w owns rows w*8 .. w*8+7 ----
    #pragma unroll
    for (int rr = 0; rr < 8; rr++) {
        int row = w * 8 + rr;
        float* p = Ps + row * 132;
        float mx = -1e30f;
        for (int j = lane; j < nj; j += 32) mx = fmaxf(mx, p[j]);
        #pragma unroll
        for (int o = 16; o; o >>= 1) mx = fmaxf(mx, __shfl_xor_sync(0xffffffffu, mx, o));
        float e4[4]; int cnt = 0; float s = 0.f;
        for (int j = lane; j < nj; j += 32) { float ev = __expf(p[j] - mx); e4[cnt++] = ev; s += ev; }
        #pragma unroll
        for (int o = 16; o; o >>= 1) s += __shfl_xor_sync(0xffffffffu, s, o);
        float inv = 1.f / s;
        cnt = 0;
        for (int j = lane; j < njc8; j += 32) {
            float val = (j < nj) ? e4[cnt++] * inv : 0.f;
            p[j] = to_tf32(val);
        }
    }

    // ================= pass 2: pl + ov =================
    float ovacc[4][4];
    #pragma unroll
    for (int nt = 0; nt < 4; nt++)
        #pragma unroll
        for (int c = 0; c < 4; c++) ovacc[nt][c] = 0.f;

    for (int ch = 0; ch < 8; ch++) {
        __syncthreads();          // lc free from prev pass2; qkc free from prev ov
        stageL(ch);
        __syncthreads();

        // pl-chunk = P @ lc
        float placc[4][4];
        #pragma unroll
        for (int nt = 0; nt < 4; nt++)
            #pragma unroll
            for (int c = 0; c < 4; c++) placc[nt][c] = 0.f;
        for (int ksj = 0; ksj < T; ksj++) {
            const float* pr = Ps + (amt * 16) * 132 + ksj * 8;
            uint32_t a[4] = { f2u(pr[g * 132 + tg]),     f2u(pr[(g + 8) * 132 + tg]),
                              f2u(pr[g * 132 + tg + 4]), f2u(pr[(g + 8) * 132 + tg + 4]) };
            #pragma unroll
            for (int nt = 0; nt < 4; nt++) {
                int tb = (ksj * 8 + anh * 4 + nt) * 68;
                uint32_t bu[2] = { f2u(lc[tb + p2o0]), f2u(lc[tb + p2o1]) };
                mma_tf32(placc[nt], a, bu);
            }
        }
        // scatter pl-chunk into qkc
        #pragma unroll
        for (int nt = 0; nt < 4; nt++) {
            int c0 = anh * 32 + nt * 8 + 2 * tg;
            #pragma unroll
            for (int e = 0; e < 4; e++) {
                int r = g + ((e >> 1) << 3);
                int c = c0 + (e & 1);
                qkc[((amt * 8 + (c >> 3)) * 32 + g * 4 + (c & 3)) * 4 +
                    ((r >> 3) + 2 * ((c >> 2) & 1))] = to_tf32(placc[nt][e]);
            }
        }
        __syncthreads();

        // ov += pl-chunk @ Wv_h-chunk^T
        {
            const float* wvb = Wvf + (size_t)(amt * 8 + anh * 4) * 4096 + ch * 512 + lane * 2;
            uint2 bp[4];
            #pragma unroll
            for (int nt = 0; nt < 4; nt++) bp[nt] = *(const uint2*)(wvb + nt * 4096);
            #pragma unroll
            for (int ksd = 0; ksd < 8; ksd++) {
                float4 af = *(const float4*)(qkc + ((amt * 8 + ksd) * 32 + lane) * 4);
                uint32_t a[4] = {f2u(af.x), f2u(af.y), f2u(af.z), f2u(af.w)};
                uint2 bc[4];
                #pragma unroll
                for (int nt = 0; nt < 4; nt++) bc[nt] = bp[nt];
                if (ksd < 7) {
                    #pragma unroll
                    for (int nt = 0; nt < 4; nt++)
                        bp[nt] = *(const uint2*)(wvb + nt * 4096 + (ksd + 1) * 64);
                }
                #pragma unroll
                for (int nt = 0; nt < 4; nt++)
                    mma_tf32(ovacc[nt], a, (const uint32_t*)&bc[nt]);
            }
        }
    }

    // ---- final store -> packed g_Af ----
    #pragma unroll
    for (int nt = 0; nt < 4; nt++) {
        int col = amt * 64 + anh * 32 + nt * 8 + 2 * tg;
        int R0 = b * 16 + g;
        g_Af[pidx(R0, col)]         = to_tf32(ovacc[nt][0]);
        g_Af[pidx(R0, col + 1)]     = to_tf32(ovacc[nt][1]);
        g_Af[pidx(R0 + 8, col)]     = to_tf32(ovacc[nt][2]);
        g_Af[pidx(R0 + 8, col + 1)] = to_tf32(ovacc[nt][3]);
    }
}

// ---------------------------------------------------------------------------
extern "C" void kernel_launch(void* const* d_in, const int* in_sizes, int n_in,
                              void* d_out, int out_size)
{
    const float* x  = (const float*)d_in[0];
    const float* l  = (const float*)d_in[1];
    const float* Wq = (const float*)d_in[2];
    const float* Wk = (const float*)d_in[3];
    const float* Wv = (const float*)d_in[4];
    const float* Wo = (const float*)d_in[5];
    const float* bo = (const float*)d_in[6];
    float* out = (float*)d_out;

    float *Qfp, *Xf, *Af, *Wqf, *Wvf, *Wof, *Wkf;
    cudaGetSymbolAddress((void**)&Qfp, g_Qf);
    cudaGetSymbolAddress((void**)&Xf,  g_Xf);
    cudaGetSymbolAddress((void**)&Af,  g_Af);
    cudaGetSymbolAddress((void**)&Wqf, g_Wqf);
    cudaGetSymbolAddress((void**)&Wvf, g_Wvf);
    cudaGetSymbolAddress((void**)&Wof, g_Wof);
    cudaGetSymbolAddress((void**)&Wkf, g_Wkf);

    const int smem_g = (8192 + 16384) * 4;   // 98304
    const int smem_f = F3_TOT * 4;           // 135168
    cudaFuncSetAttribute(gemm_f, cudaFuncAttributeMaxDynamicSharedMemorySize, smem_g);
    cudaFuncSetAttribute(fattn3, cudaFuncAttributeMaxDynamicSharedMemorySize, smem_f);

    prep_w<<<2048, 256>>>(Wq, Wk, Wv, Wo);
    prep_a<<<8192, 256>>>(x);
    // Q projection -> packed a-frag layout
    gemm_f<<<256, 512, smem_g>>>(Xf, Wqf, Qfp, nullptr, nullptr, 0, 2, 1);
    // fused head-stacked attention with absorbed K/V projections
    fattn3<<<1024, 512, smem_f>>>(Qfp, l, Wkf, Wvf);
    // output projection + bias
    gemm_f<<<256, 512, smem_g>>>(Af, Wof, out, nullptr, bo, 0, 2, 0);
}

// round 9
// speedup vs baseline: 3.8516x; 1.0264x over previous
#include <cuda_runtime.h>
#include <cstdint>
#include <cstddef>

// ---------------------------------------------------------------------------
// CrossAttentionDecoder: B=1024 (8*128), n_tok=16, num_latents=128, d=512,
// heads=8, dh=64.  Mask: batch b attends only to latents j <= (b % 128).
//
// Fully-fused formulation (Q, K, V, attn-out never materialized in DRAM):
//   per CTA (one batch b):
//     q  = x[b] @ Wq^T            (in-kernel, 16x512x512)
//     qk = q_h @ Wk_h             (per head, low-rank 64)
//     S  = qk @ l[b]^T,  P = softmax(S/8) masked
//     pl = P @ l[b]
//     ov = pl @ Wv_h^T
//     out[b] = ov @ Wo^T + bo     (in-kernel, 16x512x512)
// Launches: prep_w (weight fragment packing) + fattn4.
// ---------------------------------------------------------------------------

#define DIMK 512

__device__ float g_Wqf[64 * 64 * 32 * 2];
__device__ float g_Wvf[64 * 64 * 32 * 2];
__device__ float g_Wof[64 * 64 * 32 * 2];
__device__ float g_Wkf[8 * 64 * 8 * 32 * 2];        // transposed pack for qk

// ---------------- helpers ---------------------------------------------------
__device__ __forceinline__ float to_tf32(float x) {
    uint32_t u; asm("cvt.rna.tf32.f32 %0, %1;" : "=r"(u) : "f"(x));
    return __uint_as_float(u);
}
__device__ __forceinline__ uint32_t f2u(float x) { return __float_as_uint(x); }

__device__ __forceinline__ void mma_tf32(float* d, const uint32_t* a, const uint32_t* b) {
    asm volatile(
        "mma.sync.aligned.m16n8k8.row.col.f32.tf32.tf32.f32 "
        "{%0,%1,%2,%3}, {%4,%5,%6,%7}, {%8,%9}, {%0,%1,%2,%3};\n"
        : "+f"(d[0]), "+f"(d[1]), "+f"(d[2]), "+f"(d[3])
        : "r"(a[0]), "r"(a[1]), "r"(a[2]), "r"(a[3]),
          "r"(b[0]), "r"(b[1]));
}

// ---------------------------------------------------------------------------
// prep_w: fragment-pack Wq, Wv, Wo (B[n][k] = W[n][k]) and Wk transposed.
// ---------------------------------------------------------------------------
__global__ __launch_bounds__(256)
void prep_w(const float* __restrict__ Wq, const float* __restrict__ Wk,
            const float* __restrict__ Wv, const float* __restrict__ Wo)
{
    int gid = blockIdx.x * 256 + threadIdx.x;        // 2048 blocks
    int lane = gid & 31, kk = (gid >> 5) & 63, nv = gid >> 11;   // nv 0..255
    int g = lane >> 2, tg = lane & 3;
    if (nv < 192) {
        const float* W; float* dst; int dn;
        if (nv < 64)       { W = Wq; dst = g_Wqf; dn = nv; }
        else if (nv < 128) { W = Wv; dst = g_Wvf; dn = nv - 64; }
        else               { W = Wo; dst = g_Wof; dn = nv - 128; }
        float v0 = to_tf32(W[(size_t)(dn * 8 + g) * DIMK + kk * 8 + tg]);
        float v1 = to_tf32(W[(size_t)(dn * 8 + g) * DIMK + kk * 8 + tg + 4]);
        *(float2*)(dst + ((size_t)(dn * 64 + kk) * 32 + lane) * 2) = make_float2(v0, v1);
    } else {
        int t = nv - 192;            // 0..63
        int h = t >> 3, ks = t & 7;
        int ntg = kk;
        float v0 = to_tf32(Wk[(size_t)(h * 64 + ks * 8 + tg) * DIMK + ntg * 8 + g]);
        float v1 = to_tf32(Wk[(size_t)(h * 64 + ks * 8 + tg + 4) * DIMK + ntg * 8 + g]);
        *(float2*)(g_Wkf + ((size_t)((h * 64 + ntg) * 8 + ks) * 32 + lane) * 2) =
            make_float2(v0, v1);
    }
}

// ---------------------------------------------------------------------------
// fattn4: one CTA per batch b (heavy-first order), 512 threads.
// Smem (floats): qf 8192 | qkc 8192 | lc 8704 | Ps 128x132 = 16896
// ---------------------------------------------------------------------------
#define F4_QF  0
#define F4_QKC 8192
#define F4_LC  16384
#define F4_PS  25088
#define F4_TOT 41984      // floats -> 167936 bytes

__global__ __launch_bounds__(512, 1)
void fattn4(const float* __restrict__ x, const float* __restrict__ l,
            const float* __restrict__ bo, float* __restrict__ out)
{
    extern __shared__ __align__(16) float sm[];
    float* qf  = sm + F4_QF;
    float* qkc = sm + F4_QKC;
    float* lc  = sm + F4_LC;
    float* Ps  = sm + F4_PS;

    const int bid = blockIdx.x;
    const int b = (bid & 7) * 128 + (127 - (bid >> 3));   // heavy-first
    const int nj = (b & 127) + 1;
    const int T = (nj + 7) >> 3;
    const int njc8 = T << 3;

    const int tid = threadIdx.x, w = tid >> 5, lane = tid & 31;
    const int g = lane >> 2, tg = lane & 3;
    const int wm = w >> 2, wn = w & 3;        // scores mapping
    const int amt = w >> 1, anh = w & 1;      // phase A / pass2 / ov mapping

    // conflict-free per-lane tile read offsets (verified R8)
    const int p1o0 = g * 4 + tg;
    const int p1o1 = ((g ^ 4) + 8) * 4 + tg;
    const int h2 = g >> 2, gl = g & 3;
    const int p2o0 = ((tg ^ (h2 << 2)) + (h2 << 3)) * 4 + gl;
    const int p2o1 = (((tg + 4) ^ (h2 << 2)) + (h2 << 3)) * 4 + gl;

    // ============ prologue: stage x a-frags into qkc ============
    #pragma unroll
    for (int it = 0; it < 4; it++) {
        int idx = tid + it * 512;           // 0..2047
        int i = idx >> 7, c4 = (idx & 127) * 4;
        float4 v = *(const float4*)(x + ((size_t)(b * 16 + i)) * 512 + c4);
        float vv[4] = {v.x, v.y, v.z, v.w};
        #pragma unroll
        for (int e = 0; e < 4; e++) {
            int c = c4 + e;
            qkc[(c >> 3) * 128 + ((i & 7) * 4 + (c & 3)) * 4 +
                ((i >> 3) + 2 * ((c >> 2) & 1))] = to_tf32(vv[e]);
        }
    }
    __syncthreads();

    // ============ Q-proj: q = x @ Wq^T -> qf (per-head a-frags) ============
    {
        float acc[4][4];
        #pragma unroll
        for (int nt = 0; nt < 4; nt++)
            #pragma unroll
            for (int c = 0; c < 4; c++) acc[nt][c] = 0.f;
        const float* wqb = g_Wqf + ((size_t)(w * 4) * 64) * 64 + lane * 2;
        uint2 bp[4];
        #pragma unroll
        for (int nt = 0; nt < 4; nt++) bp[nt] = *(const uint2*)(wqb + nt * 4096);
        for (int kk = 0; kk < 64; kk++) {
            float4 af = *(const float4*)(qkc + kk * 128 + lane * 4);
            uint32_t a[4] = {f2u(af.x), f2u(af.y), f2u(af.z), f2u(af.w)};
            uint2 bc[4];
            #pragma unroll
            for (int nt = 0; nt < 4; nt++) bc[nt] = bp[nt];
            if (kk < 63) {
                #pragma unroll
                for (int nt = 0; nt < 4; nt++)
                    bp[nt] = *(const uint2*)(wqb + nt * 4096 + (kk + 1) * 64);
            }
            #pragma unroll
            for (int nt = 0; nt < 4; nt++)
                mma_tf32(acc[nt], a, (const uint32_t*)&bc[nt]);
        }
        __syncthreads();   // qkc (x-frags) dead after all warps' reads
        #pragma unroll
        for (int nt = 0; nt < 4; nt++) {
            int c0 = w * 32 + nt * 8 + 2 * tg;
            #pragma unroll
            for (int e = 0; e < 4; e++) {
                int r = g + ((e >> 1) << 3);
                int c = c0 + (e & 1);
                int h = c >> 6, ks = (c & 63) >> 3;
                qf[(h * 8 + ks) * 128 + (g * 4 + (c & 3)) * 4 +
                   ((r >> 3) + 2 * ((c >> 2) & 1))] = to_tf32(acc[nt][e]);
            }
        }
    }
    __syncthreads();

    float sacc[2][4][4];
    #pragma unroll
    for (int i = 0; i < 2; i++)
        #pragma unroll
        for (int j = 0; j < 4; j++)
            #pragma unroll
            for (int c = 0; c < 4; c++) sacc[i][j][c] = 0.f;

    // ================= pass 1: scores =================
    for (int ch = 0; ch < 8; ch++) {
        // ---- l loads first (latency overlapped by phase A) ----
        float4 sv[4];
        #pragma unroll
        for (int it = 0; it < 4; it++) {
            int idx = tid + it * 512;
            int j = idx >> 4, dq = idx & 15;
            sv[it] = make_float4(0.f, 0.f, 0.f, 0.f);
            if (j < nj)
                sv[it] = *(const float4*)(l + ((size_t)(b * 128 + j)) * 512 + ch * 64 + dq * 4);
        }
        // ---- phase A: qk-chunk = q_h @ Wk_h[:, ch*64 : +64] ----
        float aacc[4][4];
        #pragma unroll
        for (int nt = 0; nt < 4; nt++)
            #pragma unroll
            for (int c = 0; c < 4; c++) aacc[nt][c] = 0.f;
        {
            const float* wkb = g_Wkf + ((size_t)(amt * 64 + ch * 8 + anh * 4)) * 512 + lane * 2;
            const float* qa = qf + (amt * 8) * 128 + lane * 4;
            uint2 bp[4];
            #pragma unroll
            for (int nt = 0; nt < 4; nt++) bp[nt] = *(const uint2*)(wkb + nt * 512);
            #pragma unroll
            for (int ks = 0; ks < 8; ks++) {
                float4 ac = *(const float4*)(qa + ks * 128);
                uint2 bc[4];
                #pragma unroll
                for (int nt = 0; nt < 4; nt++) bc[nt] = bp[nt];
                if (ks < 7) {
                    #pragma unroll
                    for (int nt = 0; nt < 4; nt++)
                        bp[nt] = *(const uint2*)(wkb + nt * 512 + (ks + 1) * 64);
                }
                uint32_t a[4] = {f2u(ac.x), f2u(ac.y), f2u(ac.z), f2u(ac.w)};
                #pragma unroll
                for (int nt = 0; nt < 4; nt++)
                    mma_tf32(aacc[nt], a, (const uint32_t*)&bc[nt]);
            }
        }
        // scatter qk-chunk into a-frag packed qkc
        #pragma unroll
        for (int nt = 0; nt < 4; nt++) {
            int c0 = anh * 32 + nt * 8 + 2 * tg;
            #pragma unroll
            for (int e = 0; e < 4; e++) {
                int r = g + ((e >> 1) << 3);
                int c = c0 + (e & 1);
                qkc[((amt * 8 + (c >> 3)) * 32 + g * 4 + (c & 3)) * 4 +
                    ((r >> 3) + 2 * ((c >> 2) & 1))] = to_tf32(aacc[nt][e]);
            }
        }
        // ---- lc STS ----
        #pragma unroll
        for (int it = 0; it < 4; it++) {
            int idx = tid + it * 512;
            int j = idx >> 4, dq = idx & 15;
            if (j < njc8) {
                int h = dq & 1;
                int X = ((j & 7) ^ (h << 2)) + (h << 3);
                float4 o;
                o.x = to_tf32(sv[it].x); o.y = to_tf32(sv[it].y);
                o.z = to_tf32(sv[it].z); o.w = to_tf32(sv[it].w);
                *(float4*)(lc + ((j >> 3) * 8 + (dq >> 1)) * 68 + X * 4) = o;
            }
        }
        __syncthreads();

        // ---- scores mma ----
        if (wn < T) {
            #pragma unroll
            for (int ksd = 0; ksd < 8; ksd++) {
                float4 af0 = *(const float4*)(qkc + ((wm * 2 + 0) * 8 + ksd) * 128 + lane * 4);
                float4 af1 = *(const float4*)(qkc + ((wm * 2 + 1) * 8 + ksd) * 128 + lane * 4);
                uint32_t a0[4] = {f2u(af0.x), f2u(af0.y), f2u(af0.z), f2u(af0.w)};
                uint32_t a1[4] = {f2u(af1.x), f2u(af1.y), f2u(af1.z), f2u(af1.w)};
                #pragma unroll
                for (int jt4 = 0; jt4 < 4; jt4++) {
                    int jt = wn + jt4 * 4;
                    if (jt < T) {
                        int tb = (jt * 8 + ksd) * 68;
                        uint32_t bu[2] = { f2u(lc[tb + p1o0]), f2u(lc[tb + p1o1]) };
                        mma_tf32(sacc[0][jt4], a0, bu);
                        mma_tf32(sacc[1][jt4], a1, bu);
                    }
                }
            }
        }
        __syncthreads();
    }

    // ---- write scores -> Ps (scaled) ----
    if (wn < T) {
        #pragma unroll
        for (int mt = 0; mt < 2; mt++) {
            int r0 = wm * 32 + mt * 16;
            #pragma unroll
            for (int jt4 = 0; jt4 < 4; jt4++) {
                int jt = wn + jt4 * 4;
                if (jt < T) {
                    int jc = jt * 8 + 2 * tg;
                    Ps[(r0 + g) * 132 + jc]         = sacc[mt][jt4][0] * 0.125f;
                    Ps[(r0 + g) * 132 + jc + 1]     = sacc[mt][jt4][1] * 0.125f;
                    Ps[(r0 + g + 8) * 132 + jc]     = sacc[mt][jt4][2] * 0.125f;
                    Ps[(r0 + g + 8) * 132 + jc + 1] = sacc[mt][jt4][3] * 0.125f;
                }
            }
        }
    }
    __syncthreads();

    // ---- softmax: warp w owns rows w*8 .. w*8+7 ----
    #pragma unroll
    for (int rr = 0; rr < 8; rr++) {
        int row = w * 8 + rr;
        float* p = Ps + row * 132;
        float mx = -1e30f;
        for (int j = lane; j < nj; j += 32) mx = fmaxf(mx, p[j]);
        #pragma unroll
        for (int o = 16; o; o >>= 1) mx = fmaxf(mx, __shfl_xor_sync(0xffffffffu, mx, o));
        float e4[4]; int cnt = 0; float s = 0.f;
        for (int j = lane; j < nj; j += 32) { float ev = __expf(p[j] - mx); e4[cnt++] = ev; s += ev; }
        #pragma unroll
        for (int o = 16; o; o >>= 1) s += __shfl_xor_sync(0xffffffffu, s, o);
        float inv = 1.f / s;
        cnt = 0;
        for (int j = lane; j < njc8; j += 32) {
            float val = (j < nj) ? e4[cnt++] * inv : 0.f;
            p[j] = to_tf32(val);
        }
    }

    // ================= pass 2: pl + ov =================
    float ovacc[4][4];
    #pragma unroll
    for (int nt = 0; nt < 4; nt++)
        #pragma unroll
        for (int c = 0; c < 4; c++) ovacc[nt][c] = 0.f;

    for (int ch = 0; ch < 8; ch++) {
        // ---- l loads first ----
        float4 sv[4];
        #pragma unroll
        for (int it = 0; it < 4; it++) {
            int idx = tid + it * 512;
            int j = idx >> 4, dq = idx & 15;
            sv[it] = make_float4(0.f, 0.f, 0.f, 0.f);
            if (j < nj)
                sv[it] = *(const float4*)(l + ((size_t)(b * 128 + j)) * 512 + ch * 64 + dq * 4);
        }
        // ---- ov(ch-1): overlaps the loads above ----
        if (ch > 0) {
            const float* wvb = g_Wvf + (size_t)(amt * 8 + anh * 4) * 4096 + (ch - 1) * 512 + lane * 2;
            uint2 bp[4];
            #pragma unroll
            for (int nt = 0; nt < 4; nt++) bp[nt] = *(const uint2*)(wvb + nt * 4096);
            #pragma unroll
            for (int ksd = 0; ksd < 8; ksd++) {
                float4 af = *(const float4*)(qkc + ((amt * 8 + ksd) * 32 + lane) * 4);
                uint32_t a[4] = {f2u(af.x), f2u(af.y), f2u(af.z), f2u(af.w)};
                uint2 bc[4];
                #pragma unroll
                for (int nt = 0; nt < 4; nt++) bc[nt] = bp[nt];
                if (ksd < 7) {
                    #pragma unroll
                    for (int nt = 0; nt < 4; nt++)
                        bp[nt] = *(const uint2*)(wvb + nt * 4096 + (ksd + 1) * 64);
                }
                #pragma unroll
                for (int nt = 0; nt < 4; nt++)
                    mma_tf32(ovacc[nt], a, (const uint32_t*)&bc[nt]);
            }
        }
        // ---- lc STS ----
        #pragma unroll
        for (int it = 0; it < 4; it++) {
            int idx = tid + it * 512;
            int j = idx >> 4, dq = idx & 15;
            if (j < njc8) {
                int h = dq & 1;
                int X = ((j & 7) ^ (h << 2)) + (h << 3);
                float4 o;
                o.x = to_tf32(sv[it].x); o.y = to_tf32(sv[it].y);
                o.z = to_tf32(sv[it].z); o.w = to_tf32(sv[it].w);
                *(float4*)(lc + ((j >> 3) * 8 + (dq >> 1)) * 68 + X * 4) = o;
            }
        }
        __syncthreads();

        // ---- pl-chunk = P @ lc ----
        float placc[4][4];
        #pragma unroll
        for (int nt = 0; nt < 4; nt++)
            #pragma unroll
            for (int c = 0; c < 4; c++) placc[nt][c] = 0.f;
        for (int ksj = 0; ksj < T; ksj++) {
            const float* pr = Ps + (amt * 16) * 132 + ksj * 8;
            uint32_t a[4] = { f2u(pr[g * 132 + tg]),     f2u(pr[(g + 8) * 132 + tg]),
                              f2u(pr[g * 132 + tg + 4]), f2u(pr[(g + 8) * 132 + tg + 4]) };
            #pragma unroll
            for (int nt = 0; nt < 4; nt++) {
                int tb = (ksj * 8 + anh * 4 + nt) * 68;
                uint32_t bu[2] = { f2u(lc[tb + p2o0]), f2u(lc[tb + p2o1]) };
                mma_tf32(placc[nt], a, bu);
            }
        }
        // scatter pl-chunk into qkc
        #pragma unroll
        for (int nt = 0; nt < 4; nt++) {
            int c0 = anh * 32 + nt * 8 + 2 * tg;
            #pragma unroll
            for (int e = 0; e < 4; e++) {
                int r = g + ((e >> 1) << 3);
                int c = c0 + (e & 1);
                qkc[((amt * 8 + (c >> 3)) * 32 + g * 4 + (c & 3)) * 4 +
                    ((r >> 3) + 2 * ((c >> 2) & 1))] = to_tf32(placc[nt][e]);
            }
        }
        __syncthreads();
    }

    // ---- final ov(7) ----
    {
        const float* wvb = g_Wvf + (size_t)(amt * 8 + anh * 4) * 4096 + 7 * 512 + lane * 2;
        uint2 bp[4];
        #pragma unroll
        for (int nt = 0; nt < 4; nt++) bp[nt] = *(const uint2*)(wvb + nt * 4096);
        #pragma unroll
        for (int ksd = 0; ksd < 8; ksd++) {
            float4 af = *(const float4*)(qkc + ((amt * 8 + ksd) * 32 + lane) * 4);
            uint32_t a[4] = {f2u(af.x), f2u(af.y), f2u(af.z), f2u(af.w)};
            uint2 bc[4];
            #pragma unroll
            for (int nt = 0; nt < 4; nt++) bc[nt] = bp[nt];
            if (ksd < 7) {
                #pragma unroll
                for (int nt = 0; nt < 4; nt++)
                    bp[nt] = *(const uint2*)(wvb + nt * 4096 + (ksd + 1) * 64);
            }
            #pragma unroll
            for (int nt = 0; nt < 4; nt++)
                mma_tf32(ovacc[nt], a, (const uint32_t*)&bc[nt]);
        }
    }
    __syncthreads();   // all ov reads of qkc complete

    // ============ epilogue: ov -> a-frags, out = ov @ Wo^T + bo ============
    #pragma unroll
    for (int nt = 0; nt < 4; nt++) {
        int c0 = amt * 64 + anh * 32 + nt * 8 + 2 * tg;
        #pragma unroll
        for (int e = 0; e < 4; e++) {
            int r = g + ((e >> 1) << 3);          // token i
            int c = c0 + (e & 1);
            qkc[(c >> 3) * 128 + (g * 4 + (c & 3)) * 4 +
                ((r >> 3) + 2 * ((c >> 2) & 1))] = to_tf32(ovacc[nt][e]);
        }
    }
    __syncthreads();

    {
        float acc[4][4];
        #pragma unroll
        for (int nt = 0; nt < 4; nt++)
            #pragma unroll
            for (int c = 0; c < 4; c++) acc[nt][c] = 0.f;
        const float* wob = g_Wof + ((size_t)(w * 4) * 64) * 64 + lane * 2;
        uint2 bp[4];
        #pragma unroll
        for (int nt = 0; nt < 4; nt++) bp[nt] = *(const uint2*)(wob + nt * 4096);
        for (int kk = 0; kk < 64; kk++) {
            float4 af = *(const float4*)(qkc + kk * 128 + lane * 4);
            uint32_t a[4] = {f2u(af.x), f2u(af.y), f2u(af.z), f2u(af.w)};
            uint2 bc[4];
            #pragma unroll
            for (int nt = 0; nt < 4; nt++) bc[nt] = bp[nt];
            if (kk < 63) {
                #pragma unroll
                for (int nt = 0; nt < 4; nt++)
                    bp[nt] = *(const uint2*)(wob + nt * 4096 + (kk + 1) * 64);
            }
            #pragma unroll
            for (int nt = 0; nt < 4; nt++)
                mma_tf32(acc[nt], a, (const uint32_t*)&bc[nt]);
        }
        #pragma unroll
        for (int nt = 0; nt < 4; nt++) {
            int c = w * 32 + nt * 8 + 2 * tg;
            float2 bb = *(const float2*)(bo + c);
            *(float2*)(out + ((size_t)(b * 16 + g)) * 512 + c) =
                make_float2(acc[nt][0] + bb.x, acc[nt][1] + bb.y);
            *(float2*)(out + ((size_t)(b * 16 + g + 8)) * 512 + c) =
                make_float2(acc[nt][2] + bb.x, acc[nt][3] + bb.y);
        }
    }
}

// ---------------------------------------------------------------------------
extern "C" void kernel_launch(void* const* d_in, const int* in_sizes, int n_in,
                              void* d_out, int out_size)
{
    const float* x  = (const float*)d_in[0];
    const float* l  = (const float*)d_in[1];
    const float* Wq = (const float*)d_in[2];
    const float* Wk = (const float*)d_in[3];
    const float* Wv = (const float*)d_in[4];
    const float* Wo = (const float*)d_in[5];
    const float* bo = (const float*)d_in[6];
    float* out = (float*)d_out;

    const int smem_f = F4_TOT * 4;           // 167936
    cudaFuncSetAttribute(fattn4, cudaFuncAttributeMaxDynamicSharedMemorySize, smem_f);

    prep_w<<<2048, 256>>>(Wq, Wk, Wv, Wo);
    fattn4<<<1024, 512, smem_f>>>(x, l, bo, out);
}